// round 1
// baseline (speedup 1.0000x reference)
#include <cuda_runtime.h>
#include <math.h>

#define Bx 4
#define Nx 2048
#define Dx 1024
#define Hx 16
#define DHx 64
#define INNERx 1024
#define FFx 4096
#define ROWS (Bx*Nx)          // 8192

// ---------------- scratch (no allocs allowed; __device__ globals) ----------
__device__ float g_ln  [ROWS*Dx];        // 32 MB  (ln1 out, reused for ln2 out)
__device__ float g_qkv [ROWS*3*INNERx];  // 96 MB
__device__ float g_attn[ROWS*INNERx];    // 32 MB
__device__ float g_x1  [ROWS*Dx];        // 32 MB  (post-attention residual)
__device__ float g_ff1 [ROWS*FFx];       // 128 MB

// ---------------- LayerNorm: one block per row, 256 threads ---------------
__global__ __launch_bounds__(256) void ln_k(const float* __restrict__ x,
                                            const float* __restrict__ g,
                                            const float* __restrict__ b,
                                            float* __restrict__ y)
{
    int row = blockIdx.x, tid = threadIdx.x;
    const float4* xr = (const float4*)(x + (size_t)row * Dx);
    float4 v = xr[tid];
    float s = v.x + v.y + v.z + v.w;
    float q = v.x*v.x + v.y*v.y + v.z*v.z + v.w*v.w;
    #pragma unroll
    for (int o = 16; o; o >>= 1) {
        s += __shfl_xor_sync(0xffffffffu, s, o);
        q += __shfl_xor_sync(0xffffffffu, q, o);
    }
    __shared__ float ss[8], qs[8];
    if ((tid & 31) == 0) { ss[tid >> 5] = s; qs[tid >> 5] = q; }
    __syncthreads();
    s = 0.f; q = 0.f;
    #pragma unroll
    for (int w = 0; w < 8; w++) { s += ss[w]; q += qs[w]; }
    float mean = s * (1.f / Dx);
    float var  = q * (1.f / Dx) - mean * mean;
    float inv  = rsqrtf(var + 1e-5f);
    float4 gv = ((const float4*)g)[tid];
    float4 bv = ((const float4*)b)[tid];
    float4 o;
    o.x = (v.x - mean) * inv * gv.x + bv.x;
    o.y = (v.y - mean) * inv * gv.y + bv.y;
    o.z = (v.z - mean) * inv * gv.z + bv.z;
    o.w = (v.w - mean) * inv * gv.w + bv.w;
    ((float4*)(y + (size_t)row * Dx))[tid] = o;
}

// ---------------- SGEMM 128x128x8, 256 threads, 8x8 per thread ------------
// EPI: 0 = C=AB ; 1 = C=AB+bias+res ; 2 = C=gelu(AB+bias)
__device__ __forceinline__ float gelu_exact(float v) {
    return 0.5f * v * (1.0f + erff(v * 0.70710678118654752440f));
}

template<int EPI>
__global__ __launch_bounds__(256) void sgemm_k(const float* __restrict__ A,
                                               const float* __restrict__ B,
                                               float* __restrict__ C,
                                               const float* __restrict__ bias,
                                               const float* __restrict__ res,
                                               int M, int N, int K)
{
    __shared__ float As[8][128];
    __shared__ float Bs[8][128];
    int tid = threadIdx.x;
    int bm = blockIdx.y * 128, bn = blockIdx.x * 128;
    int ty = tid >> 4, tx = tid & 15;
    int rb = ty * 8, cb = tx * 8;

    int a_row = tid >> 1, a_col = (tid & 1) * 4;
    int b_row = tid >> 5, b_col = (tid & 31) * 4;
    const float* Ag = A + (size_t)(bm + a_row) * K + a_col;
    const float* Bg = B + (size_t)b_row * N + bn + b_col;

    float acc[8][8];
    #pragma unroll
    for (int i = 0; i < 8; i++)
        #pragma unroll
        for (int j = 0; j < 8; j++) acc[i][j] = 0.f;

    for (int kt = 0; kt < K; kt += 8) {
        float4 av = *(const float4*)(Ag + kt);
        float4 bv = *(const float4*)(Bg + (size_t)kt * N);
        __syncthreads();
        As[a_col + 0][a_row] = av.x;
        As[a_col + 1][a_row] = av.y;
        As[a_col + 2][a_row] = av.z;
        As[a_col + 3][a_row] = av.w;
        *(float4*)&Bs[b_row][b_col] = bv;
        __syncthreads();
        #pragma unroll
        for (int k = 0; k < 8; k++) {
            float4 a0 = *(const float4*)&As[k][rb];
            float4 a1 = *(const float4*)&As[k][rb + 4];
            float4 b0 = *(const float4*)&Bs[k][cb];
            float4 b1 = *(const float4*)&Bs[k][cb + 4];
            float ar[8] = {a0.x,a0.y,a0.z,a0.w,a1.x,a1.y,a1.z,a1.w};
            float br[8] = {b0.x,b0.y,b0.z,b0.w,b1.x,b1.y,b1.z,b1.w};
            #pragma unroll
            for (int i = 0; i < 8; i++)
                #pragma unroll
                for (int j = 0; j < 8; j++)
                    acc[i][j] += ar[i] * br[j];
        }
    }

    #pragma unroll
    for (int i = 0; i < 8; i++) {
        int gr = bm + rb + i;
        #pragma unroll
        for (int j = 0; j < 8; j++) {
            int gc = bn + cb + j;
            float v = acc[i][j];
            if (EPI >= 1) v += bias[gc];
            if (EPI == 1) v += res[(size_t)gr * N + gc];
            if (EPI == 2) v = gelu_exact(v);
            C[(size_t)gr * N + gc] = v;
        }
    }
}

// ---------------- flash attention: 64-query tile per (b,h) ----------------
// qkv rows: [ROWS][3072] = [q(1024) | k(1024) | v(1024)], head h at cols h*64
// out: [ROWS][1024] concat-head layout
__global__ __launch_bounds__(256) void flash_k(const float* __restrict__ qkv,
                                               float* __restrict__ out)
{
    extern __shared__ float sm[];
    float* Qs = sm;                 // [64][65] (transposed: [d][row])
    float* Ks = Qs + 64 * 65;       // [64][65] (transposed: [d][kv])
    float* Vs = Ks + 64 * 65;       // [64][65] (natural:    [kv][d])
    float* Ps = Vs + 64 * 65;       // [64][65]
    float* m_s = Ps + 64 * 65;      // [64]
    float* l_s = m_s + 64;          // [64]

    int qt = blockIdx.x;            // 0..31
    int bh = blockIdx.y;            // 0..63
    int b = bh >> 4, h = bh & 15;
    int tid = threadIdx.x;
    int ty = tid >> 4, tx = tid & 15;
    const float scale = 0.125f;     // DH^-0.5

    size_t base = (size_t)b * Nx * 3072;
    const float* Qg = qkv + base + (size_t)qt * 64 * 3072 + h * 64;

    // load Q transposed (coalesced: consecutive tid -> consecutive d)
    for (int i = tid; i < 64 * 64; i += 256) {
        int d = i & 63, r = i >> 6;
        Qs[d * 65 + r] = Qg[(size_t)r * 3072 + d];
    }
    if (tid < 64) { m_s[tid] = -INFINITY; l_s[tid] = 0.f; }

    float acc[4][4];
    #pragma unroll
    for (int r = 0; r < 4; r++)
        #pragma unroll
        for (int c = 0; c < 4; c++) acc[r][c] = 0.f;

    for (int j = 0; j <= qt; j++) {
        __syncthreads();   // previous P@V done with Ks/Vs; also orders Q/stat init
        const float* Kg = qkv + base + (size_t)j * 64 * 3072 + 1024 + h * 64;
        const float* Vg = qkv + base + (size_t)j * 64 * 3072 + 2048 + h * 64;
        for (int i = tid; i < 64 * 64; i += 256) {
            int d = i & 63, r = i >> 6;
            Ks[d * 65 + r] = Kg[(size_t)r * 3072 + d];
            Vs[r * 65 + d] = Vg[(size_t)r * 3072 + d];
        }
        __syncthreads();

        // S = Q K^T  (4x4 fragment)
        float s[4][4];
        #pragma unroll
        for (int r = 0; r < 4; r++)
            #pragma unroll
            for (int c = 0; c < 4; c++) s[r][c] = 0.f;
        for (int k = 0; k < 64; k++) {
            float qf[4], kf[4];
            #pragma unroll
            for (int r = 0; r < 4; r++) qf[r] = Qs[k * 65 + ty * 4 + r];
            #pragma unroll
            for (int c = 0; c < 4; c++) kf[c] = Ks[k * 65 + tx * 4 + c];
            #pragma unroll
            for (int r = 0; r < 4; r++)
                #pragma unroll
                for (int c = 0; c < 4; c++) s[r][c] += qf[r] * kf[c];
        }
        bool diag = (j == qt);
        #pragma unroll
        for (int r = 0; r < 4; r++)
            #pragma unroll
            for (int c = 0; c < 4; c++) {
                s[r][c] *= scale;
                if (diag && (tx * 4 + c > ty * 4 + r)) s[r][c] = -INFINITY;
            }

        // online softmax per row (row group = 16 tx lanes within a warp half)
        #pragma unroll
        for (int r = 0; r < 4; r++) {
            int row = ty * 4 + r;
            float mt = fmaxf(fmaxf(s[r][0], s[r][1]), fmaxf(s[r][2], s[r][3]));
            #pragma unroll
            for (int o = 1; o < 16; o <<= 1)
                mt = fmaxf(mt, __shfl_xor_sync(0xffffffffu, mt, o));
            float m_old = m_s[row];
            float m_new = fmaxf(m_old, mt);
            float al = __expf(m_old - m_new);
            float ps = 0.f;
            #pragma unroll
            for (int c = 0; c < 4; c++) {
                float p = __expf(s[r][c] - m_new);
                s[r][c] = p;
                ps += p;
            }
            #pragma unroll
            for (int o = 1; o < 16; o <<= 1)
                ps += __shfl_xor_sync(0xffffffffu, ps, o);
            #pragma unroll
            for (int c = 0; c < 4; c++) acc[r][c] *= al;
            if (tx == 0) { m_s[row] = m_new; l_s[row] = l_s[row] * al + ps; }
        }
        // write P tile
        #pragma unroll
        for (int r = 0; r < 4; r++)
            #pragma unroll
            for (int c = 0; c < 4; c++)
                Ps[(ty * 4 + r) * 65 + tx * 4 + c] = s[r][c];
        __syncthreads();

        // acc += P @ V
        for (int kk = 0; kk < 64; kk++) {
            float pf[4], vf[4];
            #pragma unroll
            for (int r = 0; r < 4; r++) pf[r] = Ps[(ty * 4 + r) * 65 + kk];
            #pragma unroll
            for (int c = 0; c < 4; c++) vf[c] = Vs[kk * 65 + tx * 4 + c];
            #pragma unroll
            for (int r = 0; r < 4; r++)
                #pragma unroll
                for (int c = 0; c < 4; c++)
                    acc[r][c] += pf[r] * vf[c];
        }
    }

    #pragma unroll
    for (int r = 0; r < 4; r++) {
        int row = ty * 4 + r;
        float inv = 1.f / l_s[row];
        size_t orow = (size_t)(b * Nx + qt * 64 + row) * INNERx + h * 64;
        #pragma unroll
        for (int c = 0; c < 4; c++)
            out[orow + tx * 4 + c] = acc[r][c] * inv;
    }
}

// ---------------- halt: halt[b] = mean_n(x2[b,n,:] . w) + b0 --------------
__global__ __launch_bounds__(256) void halt_k(const float* __restrict__ x2,
                                              const float* __restrict__ w,
                                              const float* __restrict__ b0,
                                              float* __restrict__ out)
{
    int b = blockIdx.x;
    const float* xb = x2 + (size_t)b * Nx * Dx;
    double acc = 0.0;
    for (int i = threadIdx.x; i < Nx * Dx; i += 256)
        acc += (double)xb[i] * (double)w[i & (Dx - 1)];
    __shared__ double sd[256];
    sd[threadIdx.x] = acc;
    __syncthreads();
    for (int s = 128; s > 0; s >>= 1) {
        if (threadIdx.x < s) sd[threadIdx.x] += sd[threadIdx.x + s];
        __syncthreads();
    }
    if (threadIdx.x == 0) out[b] = (float)(sd[0] / (double)Nx) + b0[0];
}

// ---------------- launch --------------------------------------------------
extern "C" void kernel_launch(void* const* d_in, const int* in_sizes, int n_in,
                              void* d_out, int out_size)
{
    const float* x     = (const float*)d_in[0];
    const float* ln1_g = (const float*)d_in[1];
    const float* ln1_b = (const float*)d_in[2];
    const float* w_qkv = (const float*)d_in[3];
    const float* w_out = (const float*)d_in[4];
    const float* b_out = (const float*)d_in[5];
    const float* ln2_g = (const float*)d_in[6];
    const float* ln2_b = (const float*)d_in[7];
    const float* w_ff1 = (const float*)d_in[8];
    const float* b_ff1 = (const float*)d_in[9];
    const float* w_ff2 = (const float*)d_in[10];
    const float* b_ff2 = (const float*)d_in[11];
    const float* w_hlt = (const float*)d_in[12];
    const float* b_hlt = (const float*)d_in[13];

    float* out_x = (float*)d_out;
    float* out_h = out_x + (size_t)Bx * Nx * Dx;

    void *p_ln, *p_qkv, *p_attn, *p_x1, *p_ff1;
    cudaGetSymbolAddress(&p_ln, g_ln);
    cudaGetSymbolAddress(&p_qkv, g_qkv);
    cudaGetSymbolAddress(&p_attn, g_attn);
    cudaGetSymbolAddress(&p_x1, g_x1);
    cudaGetSymbolAddress(&p_ff1, g_ff1);
    float* ln  = (float*)p_ln;
    float* qkv = (float*)p_qkv;
    float* att = (float*)p_attn;
    float* x1  = (float*)p_x1;
    float* ff1 = (float*)p_ff1;

    const int FLASH_SMEM = (4 * 64 * 65 + 128) * (int)sizeof(float); // 67584 B
    cudaFuncSetAttribute(flash_k, cudaFuncAttributeMaxDynamicSharedMemorySize,
                         FLASH_SMEM);

    // 1. LN1
    ln_k<<<ROWS, 256>>>(x, ln1_g, ln1_b, ln);
    // 2. QKV = ln @ w_qkv   [8192,1024]x[1024,3072]
    sgemm_k<0><<<dim3(3 * INNERx / 128, ROWS / 128), 256>>>(
        ln, w_qkv, qkv, nullptr, nullptr, ROWS, 3 * INNERx, Dx);
    // 3. causal flash attention
    flash_k<<<dim3(Nx / 64, Bx * Hx), 256, FLASH_SMEM>>>(qkv, att);
    // 4. x1 = att @ w_out + b_out + x
    sgemm_k<1><<<dim3(Dx / 128, ROWS / 128), 256>>>(
        att, w_out, x1, b_out, x, ROWS, Dx, INNERx);
    // 5. LN2
    ln_k<<<ROWS, 256>>>(x1, ln2_g, ln2_b, ln);
    // 6. ff1 = gelu(ln @ w_ff1 + b_ff1)
    sgemm_k<2><<<dim3(FFx / 128, ROWS / 128), 256>>>(
        ln, w_ff1, ff1, b_ff1, nullptr, ROWS, FFx, Dx);
    // 7. x2 = ff1 @ w_ff2 + b_ff2 + x1   -> d_out
    sgemm_k<1><<<dim3(Dx / 128, ROWS / 128), 256>>>(
        ff1, w_ff2, out_x, b_ff2, x1, ROWS, Dx, FFx);
    // 8. halt
    halt_k<<<Bx, 256>>>(out_x, w_hlt, b_hlt, out_h);
}

// round 3
// speedup vs baseline: 1.8116x; 1.8116x over previous
#include <cuda_runtime.h>
#include <math.h>
#include <stdint.h>

#define Bx 4
#define Nx 2048
#define Dx 1024
#define Hx 16
#define DHx 64
#define INNERx 1024
#define FFx 4096
#define ROWS (Bx*Nx)          // 8192

// ---------------- scratch (no allocs allowed; __device__ globals) ----------
__device__ float g_ln   [ROWS*Dx];         // ln1 out, reused for ln2 out
__device__ float g_qkv  [ROWS*3*INNERx];
__device__ float g_attn [ROWS*INNERx];
__device__ float g_x1   [ROWS*Dx];
__device__ float g_ff1  [ROWS*FFx];
__device__ float g_wqkvT[3*INNERx*Dx];     // [3072][1024] K-major
__device__ float g_woutT[Dx*INNERx];       // [1024][1024]
__device__ float g_wff1T[FFx*Dx];          // [4096][1024]
__device__ float g_wff2T[Dx*FFx];          // [1024][4096]

// ---------------- helpers --------------------------------------------------
__device__ __forceinline__ uint32_t u32ptr(const void* p) {
    uint32_t a;
    asm("{ .reg .u64 t; cvta.to.shared.u64 t, %1; cvt.u32.u64 %0, t; }"
        : "=r"(a) : "l"(p));
    return a;
}
__device__ __forceinline__ float rtf32(float x) {
    uint32_t r;
    asm("cvt.rna.tf32.f32 %0, %1;" : "=r"(r) : "f"(x));
    return __uint_as_float(r);
}
__device__ __forceinline__ float gelu_exact(float v) {
    return 0.5f * v * (1.0f + erff(v * 0.70710678118654752440f));
}

#define CP_ASYNC16(dst, src) \
    asm volatile("cp.async.cg.shared.global [%0], [%1], 16;" :: "r"(dst), "l"(src))
#define CP_COMMIT() asm volatile("cp.async.commit_group;" ::: "memory")
#define CP_WAIT1()  asm volatile("cp.async.wait_group 1;" ::: "memory")
#define CP_WAIT0()  asm volatile("cp.async.wait_group 0;" ::: "memory")

__device__ __forceinline__ void mma_tf32_16x8x8(float* d, const uint32_t* a,
                                                const uint32_t* b) {
    asm volatile(
        "mma.sync.aligned.m16n8k8.row.col.f32.tf32.tf32.f32 "
        "{%0,%1,%2,%3}, {%4,%5,%6,%7}, {%8,%9}, {%0,%1,%2,%3};"
        : "+f"(d[0]), "+f"(d[1]), "+f"(d[2]), "+f"(d[3])
        : "r"(a[0]), "r"(a[1]), "r"(a[2]), "r"(a[3]), "r"(b[0]), "r"(b[1]));
}

// ---------------- LayerNorm (outputs rounded to tf32) ---------------------
__global__ __launch_bounds__(256) void ln_k(const float* __restrict__ x,
                                            const float* __restrict__ g,
                                            const float* __restrict__ b,
                                            float* __restrict__ y)
{
    int row = blockIdx.x, tid = threadIdx.x;
    const float4* xr = (const float4*)(x + (size_t)row * Dx);
    float4 v = xr[tid];
    float s = v.x + v.y + v.z + v.w;
    float q = v.x*v.x + v.y*v.y + v.z*v.z + v.w*v.w;
    #pragma unroll
    for (int o = 16; o; o >>= 1) {
        s += __shfl_xor_sync(0xffffffffu, s, o);
        q += __shfl_xor_sync(0xffffffffu, q, o);
    }
    __shared__ float ss[8], qs[8];
    if ((tid & 31) == 0) { ss[tid >> 5] = s; qs[tid >> 5] = q; }
    __syncthreads();
    s = 0.f; q = 0.f;
    #pragma unroll
    for (int w = 0; w < 8; w++) { s += ss[w]; q += qs[w]; }
    float mean = s * (1.f / Dx);
    float var  = q * (1.f / Dx) - mean * mean;
    float inv  = rsqrtf(var + 1e-5f);
    float4 gv = ((const float4*)g)[tid];
    float4 bv = ((const float4*)b)[tid];
    float4 o;
    o.x = rtf32((v.x - mean) * inv * gv.x + bv.x);
    o.y = rtf32((v.y - mean) * inv * gv.y + bv.y);
    o.z = rtf32((v.z - mean) * inv * gv.z + bv.z);
    o.w = rtf32((v.w - mean) * inv * gv.w + bv.w);
    ((float4*)(y + (size_t)row * Dx))[tid] = o;
}

// ---------------- weight transpose W[K][N] -> WT[N][K] (tf32-rounded) -----
__global__ __launch_bounds__(256) void transpose_k(const float* __restrict__ W,
                                                   float* __restrict__ WT,
                                                   int K, int N)
{
    __shared__ float t[32][33];
    int n0 = blockIdx.x * 32, k0 = blockIdx.y * 32;
    int tx = threadIdx.x, ty = threadIdx.y;
    #pragma unroll
    for (int i = ty; i < 32; i += 8)
        t[i][tx] = W[(size_t)(k0 + i) * N + n0 + tx];
    __syncthreads();
    #pragma unroll
    for (int i = ty; i < 32; i += 8)
        WT[(size_t)(n0 + i) * K + k0 + tx] = rtf32(t[tx][i]);
}

// ---------------- tf32 mma.sync GEMM: 128x128 CTA tile --------------------
// C[M,N] = A[M,K] @ BT[N,K]^T.  EPI: 0=plain, 1=+bias+res, 2=tf32(gelu(+bias))
// smem tiles stored [row][k] with row stride 36 floats (conflict-free frags)
#define STGf (128*36)                      // floats per tile
#define GEMM_SMEM (2*2*STGf*4)             // 73728 bytes

template<int EPI>
__global__ __launch_bounds__(256) void mma_gemm(
    const float* __restrict__ A, const float* __restrict__ BT,
    float* __restrict__ C, const float* __restrict__ bias,
    const float* __restrict__ res, int M, int N, int K)
{
    extern __shared__ float sm[];
    int tid = threadIdx.x, lane = tid & 31, warp = tid >> 5;
    int bm = blockIdx.y * 128, bn = blockIdx.x * 128;
    int wm = (warp & 1) * 64, wn = (warp >> 1) * 32;
    int g = lane >> 2, t4 = lane & 3;

    float acc[4][4][4];
    #pragma unroll
    for (int mi = 0; mi < 4; mi++)
        #pragma unroll
        for (int ni = 0; ni < 4; ni++)
            #pragma unroll
            for (int r = 0; r < 4; r++) acc[mi][ni][r] = 0.f;

    uint32_t sb = u32ptr(sm);
    int r0 = tid >> 3, c4 = (tid & 7) * 4;
    int nK = K >> 5;

    // prologue: stages 0,1
    #pragma unroll
    for (int s = 0; s < 2; s++) {
        int kt = s * 32;
        #pragma unroll
        for (int it = 0; it < 4; it++) {
            int row = r0 + it * 32;
            CP_ASYNC16(sb + (s*2*STGf + row*36 + c4)*4,
                       A  + (size_t)(bm + row) * K + kt + c4);
            CP_ASYNC16(sb + (s*2*STGf + STGf + row*36 + c4)*4,
                       BT + (size_t)(bn + row) * K + kt + c4);
        }
        CP_COMMIT();
    }

    for (int i = 0; i < nK; i++) {
        int st = i & 1;
        if (i + 2 < nK) CP_WAIT1(); else CP_WAIT0();
        __syncthreads();
        const float* As = sm + st * 2 * STGf;
        const float* Bs = As + STGf;

        #pragma unroll
        for (int ks = 0; ks < 4; ks++) {
            int k = ks * 8;
            uint32_t af[4][4], bf[4][2];
            #pragma unroll
            for (int mi = 0; mi < 4; mi++) {
                const float* ap = As + (wm + 16*mi + g) * 36 + k + t4;
                af[mi][0] = __float_as_uint(ap[0]);
                af[mi][1] = __float_as_uint(ap[8*36]);
                af[mi][2] = __float_as_uint(ap[4]);
                af[mi][3] = __float_as_uint(ap[8*36 + 4]);
            }
            #pragma unroll
            for (int ni = 0; ni < 4; ni++) {
                const float* bp = Bs + (wn + 8*ni + g) * 36 + k + t4;
                bf[ni][0] = __float_as_uint(bp[0]);
                bf[ni][1] = __float_as_uint(bp[4]);
            }
            #pragma unroll
            for (int mi = 0; mi < 4; mi++)
                #pragma unroll
                for (int ni = 0; ni < 4; ni++)
                    mma_tf32_16x8x8(acc[mi][ni], af[mi], bf[ni]);
        }
        __syncthreads();

        int nx = i + 2;
        if (nx < nK) {
            int kt = nx * 32;
            #pragma unroll
            for (int it = 0; it < 4; it++) {
                int row = r0 + it * 32;
                CP_ASYNC16(sb + (st*2*STGf + row*36 + c4)*4,
                           A  + (size_t)(bm + row) * K + kt + c4);
                CP_ASYNC16(sb + (st*2*STGf + STGf + row*36 + c4)*4,
                           BT + (size_t)(bn + row) * K + kt + c4);
            }
            CP_COMMIT();
        }
    }

    // epilogue: direct float2 stores
    #pragma unroll
    for (int mi = 0; mi < 4; mi++) {
        #pragma unroll
        for (int ni = 0; ni < 4; ni++) {
            int col = bn + wn + 8*ni + 2*t4;
            #pragma unroll
            for (int h = 0; h < 2; h++) {
                int row = bm + wm + 16*mi + g + 8*h;
                float v0 = acc[mi][ni][2*h + 0];
                float v1 = acc[mi][ni][2*h + 1];
                if (EPI >= 1) { v0 += bias[col]; v1 += bias[col + 1]; }
                if (EPI == 1) {
                    float2 rr = *(const float2*)(res + (size_t)row * N + col);
                    v0 += rr.x; v1 += rr.y;
                }
                if (EPI == 2) {
                    v0 = rtf32(gelu_exact(v0));
                    v1 = rtf32(gelu_exact(v1));
                }
                *(float2*)(C + (size_t)row * N + col) = make_float2(v0, v1);
            }
        }
    }
}

// ---------------- flash attention: 64-query tile per (b,h) ----------------
__global__ __launch_bounds__(256) void flash_k(const float* __restrict__ qkv,
                                               float* __restrict__ out)
{
    extern __shared__ float sm[];
    float* Qs = sm;
    float* Ks = Qs + 64 * 65;
    float* Vs = Ks + 64 * 65;
    float* Ps = Vs + 64 * 65;
    float* m_s = Ps + 64 * 65;
    float* l_s = m_s + 64;

    int qt = blockIdx.x;
    int bh = blockIdx.y;
    int b = bh >> 4, h = bh & 15;
    int tid = threadIdx.x;
    int ty = tid >> 4, tx = tid & 15;
    const float scale = 0.125f;

    size_t base = (size_t)b * Nx * 3072;
    const float* Qg = qkv + base + (size_t)qt * 64 * 3072 + h * 64;

    for (int i = tid; i < 64 * 64; i += 256) {
        int d = i & 63, r = i >> 6;
        Qs[d * 65 + r] = Qg[(size_t)r * 3072 + d];
    }
    if (tid < 64) { m_s[tid] = -INFINITY; l_s[tid] = 0.f; }

    float acc[4][4];
    #pragma unroll
    for (int r = 0; r < 4; r++)
        #pragma unroll
        for (int c = 0; c < 4; c++) acc[r][c] = 0.f;

    for (int j = 0; j <= qt; j++) {
        __syncthreads();
        const float* Kg = qkv + base + (size_t)j * 64 * 3072 + 1024 + h * 64;
        const float* Vg = qkv + base + (size_t)j * 64 * 3072 + 2048 + h * 64;
        for (int i = tid; i < 64 * 64; i += 256) {
            int d = i & 63, r = i >> 6;
            Ks[d * 65 + r] = Kg[(size_t)r * 3072 + d];
            Vs[r * 65 + d] = Vg[(size_t)r * 3072 + d];
        }
        __syncthreads();

        float s[4][4];
        #pragma unroll
        for (int r = 0; r < 4; r++)
            #pragma unroll
            for (int c = 0; c < 4; c++) s[r][c] = 0.f;
        for (int k = 0; k < 64; k++) {
            float qf[4], kf[4];
            #pragma unroll
            for (int r = 0; r < 4; r++) qf[r] = Qs[k * 65 + ty * 4 + r];
            #pragma unroll
            for (int c = 0; c < 4; c++) kf[c] = Ks[k * 65 + tx * 4 + c];
            #pragma unroll
            for (int r = 0; r < 4; r++)
                #pragma unroll
                for (int c = 0; c < 4; c++) s[r][c] += qf[r] * kf[c];
        }
        bool diag = (j == qt);
        #pragma unroll
        for (int r = 0; r < 4; r++)
            #pragma unroll
            for (int c = 0; c < 4; c++) {
                s[r][c] *= scale;
                if (diag && (tx * 4 + c > ty * 4 + r)) s[r][c] = -INFINITY;
            }

        #pragma unroll
        for (int r = 0; r < 4; r++) {
            int row = ty * 4 + r;
            float mt = fmaxf(fmaxf(s[r][0], s[r][1]), fmaxf(s[r][2], s[r][3]));
            #pragma unroll
            for (int o = 1; o < 16; o <<= 1)
                mt = fmaxf(mt, __shfl_xor_sync(0xffffffffu, mt, o));
            float m_old = m_s[row];
            float m_new = fmaxf(m_old, mt);
            float al = __expf(m_old - m_new);
            float ps = 0.f;
            #pragma unroll
            for (int c = 0; c < 4; c++) {
                float p = __expf(s[r][c] - m_new);
                s[r][c] = p;
                ps += p;
            }
            #pragma unroll
            for (int o = 1; o < 16; o <<= 1)
                ps += __shfl_xor_sync(0xffffffffu, ps, o);
            #pragma unroll
            for (int c = 0; c < 4; c++) acc[r][c] *= al;
            if (tx == 0) { m_s[row] = m_new; l_s[row] = l_s[row] * al + ps; }
        }
        #pragma unroll
        for (int r = 0; r < 4; r++)
            #pragma unroll
            for (int c = 0; c < 4; c++)
                Ps[(ty * 4 + r) * 65 + tx * 4 + c] = s[r][c];
        __syncthreads();

        for (int kk = 0; kk < 64; kk++) {
            float pf[4], vf[4];
            #pragma unroll
            for (int r = 0; r < 4; r++) pf[r] = Ps[(ty * 4 + r) * 65 + kk];
            #pragma unroll
            for (int c = 0; c < 4; c++) vf[c] = Vs[kk * 65 + tx * 4 + c];
            #pragma unroll
            for (int r = 0; r < 4; r++)
                #pragma unroll
                for (int c = 0; c < 4; c++)
                    acc[r][c] += pf[r] * vf[c];
        }
    }

    #pragma unroll
    for (int r = 0; r < 4; r++) {
        int row = ty * 4 + r;
        float inv = 1.f / l_s[row];
        size_t orow = (size_t)(b * Nx + qt * 64 + row) * INNERx + h * 64;
        #pragma unroll
        for (int c = 0; c < 4; c++)
            out[orow + tx * 4 + c] = rtf32(acc[r][c] * inv);
    }
}

// ---------------- halt ----------------------------------------------------
__global__ __launch_bounds__(256) void halt_k(const float* __restrict__ x2,
                                              const float* __restrict__ w,
                                              const float* __restrict__ b0,
                                              float* __restrict__ out)
{
    int b = blockIdx.x;
    const float* xb = x2 + (size_t)b * Nx * Dx;
    double acc = 0.0;
    for (int i = threadIdx.x; i < Nx * Dx; i += 256)
        acc += (double)xb[i] * (double)w[i & (Dx - 1)];
    __shared__ double sd[256];
    sd[threadIdx.x] = acc;
    __syncthreads();
    for (int s = 128; s > 0; s >>= 1) {
        if (threadIdx.x < s) sd[threadIdx.x] += sd[threadIdx.x + s];
        __syncthreads();
    }
    if (threadIdx.x == 0) out[b] = (float)(sd[0] / (double)Nx) + b0[0];
}

// ---------------- launch --------------------------------------------------
extern "C" void kernel_launch(void* const* d_in, const int* in_sizes, int n_in,
                              void* d_out, int out_size)
{
    const float* x     = (const float*)d_in[0];
    const float* ln1_g = (const float*)d_in[1];
    const float* ln1_b = (const float*)d_in[2];
    const float* w_qkv = (const float*)d_in[3];
    const float* w_out = (const float*)d_in[4];
    const float* b_out = (const float*)d_in[5];
    const float* ln2_g = (const float*)d_in[6];
    const float* ln2_b = (const float*)d_in[7];
    const float* w_ff1 = (const float*)d_in[8];
    const float* b_ff1 = (const float*)d_in[9];
    const float* w_ff2 = (const float*)d_in[10];
    const float* b_ff2 = (const float*)d_in[11];
    const float* w_hlt = (const float*)d_in[12];
    const float* b_hlt = (const float*)d_in[13];

    float* out_x = (float*)d_out;
    float* out_h = out_x + (size_t)Bx * Nx * Dx;

    void *p_ln, *p_qkv, *p_attn, *p_x1, *p_ff1;
    void *p_wqkvT, *p_woutT, *p_wff1T, *p_wff2T;
    cudaGetSymbolAddress(&p_ln, g_ln);
    cudaGetSymbolAddress(&p_qkv, g_qkv);
    cudaGetSymbolAddress(&p_attn, g_attn);
    cudaGetSymbolAddress(&p_x1, g_x1);
    cudaGetSymbolAddress(&p_ff1, g_ff1);
    cudaGetSymbolAddress(&p_wqkvT, g_wqkvT);
    cudaGetSymbolAddress(&p_woutT, g_woutT);
    cudaGetSymbolAddress(&p_wff1T, g_wff1T);
    cudaGetSymbolAddress(&p_wff2T, g_wff2T);
    float* ln  = (float*)p_ln;
    float* qkv = (float*)p_qkv;
    float* att = (float*)p_attn;
    float* x1  = (float*)p_x1;
    float* ff1 = (float*)p_ff1;

    const int FLASH_SMEM = (4 * 64 * 65 + 128) * (int)sizeof(float);
    cudaFuncSetAttribute(flash_k, cudaFuncAttributeMaxDynamicSharedMemorySize,
                         FLASH_SMEM);
    cudaFuncSetAttribute(mma_gemm<0>, cudaFuncAttributeMaxDynamicSharedMemorySize, GEMM_SMEM);
    cudaFuncSetAttribute(mma_gemm<1>, cudaFuncAttributeMaxDynamicSharedMemorySize, GEMM_SMEM);
    cudaFuncSetAttribute(mma_gemm<2>, cudaFuncAttributeMaxDynamicSharedMemorySize, GEMM_SMEM);

    // 0. weight transposes (tf32-rounded, K-major)
    transpose_k<<<dim3(3*INNERx/32, Dx/32), dim3(32, 8)>>>(w_qkv, (float*)p_wqkvT, Dx, 3*INNERx);
    transpose_k<<<dim3(Dx/32, INNERx/32),   dim3(32, 8)>>>(w_out, (float*)p_woutT, INNERx, Dx);
    transpose_k<<<dim3(FFx/32, Dx/32),      dim3(32, 8)>>>(w_ff1, (float*)p_wff1T, Dx, FFx);
    transpose_k<<<dim3(Dx/32, FFx/32),      dim3(32, 8)>>>(w_ff2, (float*)p_wff2T, FFx, Dx);

    // 1. LN1
    ln_k<<<ROWS, 256>>>(x, ln1_g, ln1_b, ln);
    // 2. QKV = ln @ w_qkv
    mma_gemm<0><<<dim3(3*INNERx/128, ROWS/128), 256, GEMM_SMEM>>>(
        ln, (const float*)p_wqkvT, qkv, nullptr, nullptr, ROWS, 3*INNERx, Dx);
    // 3. causal flash attention
    flash_k<<<dim3(Nx/64, Bx*Hx), 256, FLASH_SMEM>>>(qkv, att);
    // 4. x1 = att @ w_out + b_out + x
    mma_gemm<1><<<dim3(Dx/128, ROWS/128), 256, GEMM_SMEM>>>(
        att, (const float*)p_woutT, x1, b_out, x, ROWS, Dx, INNERx);
    // 5. LN2
    ln_k<<<ROWS, 256>>>(x1, ln2_g, ln2_b, ln);
    // 6. ff1 = gelu(ln @ w_ff1 + b_ff1)
    mma_gemm<2><<<dim3(FFx/128, ROWS/128), 256, GEMM_SMEM>>>(
        ln, (const float*)p_wff1T, ff1, b_ff1, nullptr, ROWS, FFx, Dx);
    // 7. x2 = ff1 @ w_ff2 + b_ff2 + x1 -> d_out
    mma_gemm<1><<<dim3(Dx/128, ROWS/128), 256, GEMM_SMEM>>>(
        ff1, (const float*)p_wff2T, out_x, b_ff2, x1, ROWS, Dx, FFx);
    // 8. halt
    halt_k<<<Bx, 256>>>(out_x, w_hlt, b_hlt, out_h);
}

// round 4
// speedup vs baseline: 2.4113x; 1.3310x over previous
#include <cuda_runtime.h>
#include <math.h>
#include <stdint.h>

#define Bx 4
#define Nx 2048
#define Dx 1024
#define Hx 16
#define DHx 64
#define INNERx 1024
#define FFx 4096
#define ROWS (Bx*Nx)          // 8192

// ---------------- scratch ---------------------------------------------------
__device__ float g_ln   [ROWS*Dx];
__device__ float g_qkv  [ROWS*3*INNERx];
__device__ float g_attn [ROWS*INNERx];
__device__ float g_x1   [ROWS*Dx];
__device__ float g_ff1  [ROWS*FFx];
__device__ float g_wqkvT[3*INNERx*Dx];
__device__ float g_woutT[Dx*INNERx];
__device__ float g_wff1T[FFx*Dx];
__device__ float g_wff2T[Dx*FFx];

// ---------------- helpers ---------------------------------------------------
__device__ __forceinline__ uint32_t u32ptr(const void* p) {
    uint32_t a;
    asm("{ .reg .u64 t; cvta.to.shared.u64 t, %1; cvt.u32.u64 %0, t; }"
        : "=r"(a) : "l"(p));
    return a;
}
__device__ __forceinline__ float rtf32(float x) {
    uint32_t r;
    asm("cvt.rna.tf32.f32 %0, %1;" : "=r"(r) : "f"(x));
    return __uint_as_float(r);
}
__device__ __forceinline__ float gelu_exact(float v) {
    return 0.5f * v * (1.0f + erff(v * 0.70710678118654752440f));
}

#define CP_ASYNC16(dst, src) \
    asm volatile("cp.async.cg.shared.global [%0], [%1], 16;" :: "r"(dst), "l"(src))
#define CP_COMMIT() asm volatile("cp.async.commit_group;" ::: "memory")
#define CP_WAIT1()  asm volatile("cp.async.wait_group 1;" ::: "memory")
#define CP_WAIT0()  asm volatile("cp.async.wait_group 0;" ::: "memory")

__device__ __forceinline__ void mma_tf32_16x8x8(float* d, const uint32_t* a,
                                                const uint32_t* b) {
    asm volatile(
        "mma.sync.aligned.m16n8k8.row.col.f32.tf32.tf32.f32 "
        "{%0,%1,%2,%3}, {%4,%5,%6,%7}, {%8,%9}, {%0,%1,%2,%3};"
        : "+f"(d[0]), "+f"(d[1]), "+f"(d[2]), "+f"(d[3])
        : "r"(a[0]), "r"(a[1]), "r"(a[2]), "r"(a[3]), "r"(b[0]), "r"(b[1]));
}

// ---------------- LayerNorm -------------------------------------------------
__global__ __launch_bounds__(256) void ln_k(const float* __restrict__ x,
                                            const float* __restrict__ g,
                                            const float* __restrict__ b,
                                            float* __restrict__ y)
{
    int row = blockIdx.x, tid = threadIdx.x;
    const float4* xr = (const float4*)(x + (size_t)row * Dx);
    float4 v = xr[tid];
    float s = v.x + v.y + v.z + v.w;
    float q = v.x*v.x + v.y*v.y + v.z*v.z + v.w*v.w;
    #pragma unroll
    for (int o = 16; o; o >>= 1) {
        s += __shfl_xor_sync(0xffffffffu, s, o);
        q += __shfl_xor_sync(0xffffffffu, q, o);
    }
    __shared__ float ss[8], qs[8];
    if ((tid & 31) == 0) { ss[tid >> 5] = s; qs[tid >> 5] = q; }
    __syncthreads();
    s = 0.f; q = 0.f;
    #pragma unroll
    for (int w = 0; w < 8; w++) { s += ss[w]; q += qs[w]; }
    float mean = s * (1.f / Dx);
    float var  = q * (1.f / Dx) - mean * mean;
    float inv  = rsqrtf(var + 1e-5f);
    float4 gv = ((const float4*)g)[tid];
    float4 bv = ((const float4*)b)[tid];
    float4 o;
    o.x = rtf32((v.x - mean) * inv * gv.x + bv.x);
    o.y = rtf32((v.y - mean) * inv * gv.y + bv.y);
    o.z = rtf32((v.z - mean) * inv * gv.z + bv.z);
    o.w = rtf32((v.w - mean) * inv * gv.w + bv.w);
    ((float4*)(y + (size_t)row * Dx))[tid] = o;
}

// ---------------- weight transpose -----------------------------------------
__global__ __launch_bounds__(256) void transpose_k(const float* __restrict__ W,
                                                   float* __restrict__ WT,
                                                   int K, int N)
{
    __shared__ float t[32][33];
    int n0 = blockIdx.x * 32, k0 = blockIdx.y * 32;
    int tx = threadIdx.x, ty = threadIdx.y;
    #pragma unroll
    for (int i = ty; i < 32; i += 8)
        t[i][tx] = W[(size_t)(k0 + i) * N + n0 + tx];
    __syncthreads();
    #pragma unroll
    for (int i = ty; i < 32; i += 8)
        WT[(size_t)(n0 + i) * K + k0 + tx] = rtf32(t[tx][i]);
}

// ---------------- tf32 mma GEMM: 128x256 CTA, 8 warps of 64x64, 3 stages ---
#define ASTRf (128*36)
#define BSTRf (256*36)
#define STGf  (ASTRf + BSTRf)               // 13824 floats / stage
#define GEMM_SMEM (3*STGf*4)                // 165888 bytes

template<int EPI>
__global__ __launch_bounds__(256) void mma_gemm(
    const float* __restrict__ A, const float* __restrict__ BT,
    float* __restrict__ C, const float* __restrict__ bias,
    const float* __restrict__ res, int M, int N, int K)
{
    extern __shared__ float sm[];
    int tid = threadIdx.x, lane = tid & 31, warp = tid >> 5;
    int bm = blockIdx.y * 128, bn = blockIdx.x * 256;
    int wm = (warp >> 2) * 64, wn = (warp & 3) * 64;
    int g = lane >> 2, t4 = lane & 3;

    float acc[4][8][4];
    #pragma unroll
    for (int mi = 0; mi < 4; mi++)
        #pragma unroll
        for (int ni = 0; ni < 8; ni++)
            #pragma unroll
            for (int r = 0; r < 4; r++) acc[mi][ni][r] = 0.f;

    uint32_t sb = u32ptr(sm);
    int r0 = tid >> 3, c4 = (tid & 7) * 4;
    int nK = K >> 5;

    // prologue: chunks 0,1 into slots 0,1
    #pragma unroll
    for (int s = 0; s < 2; s++) {
        int kt = s * 32;
        #pragma unroll
        for (int it = 0; it < 4; it++) {
            int row = r0 + it * 32;
            CP_ASYNC16(sb + (s*STGf + row*36 + c4)*4,
                       A + (size_t)(bm + row) * K + kt + c4);
        }
        #pragma unroll
        for (int it = 0; it < 8; it++) {
            int row = r0 + it * 32;
            CP_ASYNC16(sb + (s*STGf + ASTRf + row*36 + c4)*4,
                       BT + (size_t)(bn + row) * K + kt + c4);
        }
        CP_COMMIT();
    }

    for (int i = 0; i < nK; i++) {
        int slot = i % 3;
        if (i + 2 < nK) CP_WAIT1(); else CP_WAIT0();
        __syncthreads();

        // prefetch chunk i+2 into slot (i+2)%3 (overlaps with compute below)
        int nx = i + 2;
        if (nx < nK) {
            int ns = nx % 3, kt = nx * 32;
            #pragma unroll
            for (int it = 0; it < 4; it++) {
                int row = r0 + it * 32;
                CP_ASYNC16(sb + (ns*STGf + row*36 + c4)*4,
                           A + (size_t)(bm + row) * K + kt + c4);
            }
            #pragma unroll
            for (int it = 0; it < 8; it++) {
                int row = r0 + it * 32;
                CP_ASYNC16(sb + (ns*STGf + ASTRf + row*36 + c4)*4,
                           BT + (size_t)(bn + row) * K + kt + c4);
            }
            CP_COMMIT();
        }

        const float* As = sm + slot * STGf;
        const float* Bs = As + ASTRf;
        #pragma unroll
        for (int ks = 0; ks < 4; ks++) {
            int k = ks * 8;
            uint32_t af[4][4];
            #pragma unroll
            for (int mi = 0; mi < 4; mi++) {
                const float* ap = As + (wm + 16*mi + g) * 36 + k + t4;
                af[mi][0] = __float_as_uint(ap[0]);
                af[mi][1] = __float_as_uint(ap[8*36]);
                af[mi][2] = __float_as_uint(ap[4]);
                af[mi][3] = __float_as_uint(ap[8*36 + 4]);
            }
            #pragma unroll
            for (int ni = 0; ni < 8; ni++) {
                const float* bp = Bs + (wn + 8*ni + g) * 36 + k + t4;
                uint32_t bf[2];
                bf[0] = __float_as_uint(bp[0]);
                bf[1] = __float_as_uint(bp[4]);
                #pragma unroll
                for (int mi = 0; mi < 4; mi++)
                    mma_tf32_16x8x8(acc[mi][ni], af[mi], bf);
            }
        }
    }

    // epilogue
    #pragma unroll
    for (int mi = 0; mi < 4; mi++) {
        #pragma unroll
        for (int ni = 0; ni < 8; ni++) {
            int col = bn + wn + 8*ni + 2*t4;
            #pragma unroll
            for (int h = 0; h < 2; h++) {
                int row = bm + wm + 16*mi + g + 8*h;
                float v0 = acc[mi][ni][2*h + 0];
                float v1 = acc[mi][ni][2*h + 1];
                if (EPI >= 1) { v0 += bias[col]; v1 += bias[col + 1]; }
                if (EPI == 1) {
                    float2 rr = *(const float2*)(res + (size_t)row * N + col);
                    v0 += rr.x; v1 += rr.y;
                }
                if (EPI == 2) { v0 = rtf32(gelu_exact(v0)); v1 = rtf32(gelu_exact(v1)); }
                if (EPI == 0) { v0 = rtf32(v0); v1 = rtf32(v1); }
                *(float2*)(C + (size_t)row * N + col) = make_float2(v0, v1);
            }
        }
    }
}

// ---------------- flash attention on tensor cores ---------------------------
// 128 threads (4 warps), 64-query tile per (b,h). K/V double-buffered cp.async.
// smem floats: Ks0 @0, Ks1 @4352, Vs0 @8704, Vs1 @13056, Ps @17408 (stride 68)
#define FTILE (64*68)
#define FLASH_SMEM (5*FTILE*4)              // 87040 bytes

__global__ __launch_bounds__(128) void flashm_k(const float* __restrict__ qkv,
                                                float* __restrict__ out)
{
    extern __shared__ float fsm[];
    float* Ps = fsm + 4 * FTILE;
    uint32_t sb = u32ptr(fsm);

    int qt = blockIdx.x, bh = blockIdx.y;
    int b = bh >> 4, h = bh & 15;
    int tid = threadIdx.x, lane = tid & 31, warp = tid >> 5;
    int g = lane >> 2, t4 = lane & 3;
    const float scale = 0.125f;

    size_t base = (size_t)b * Nx * 3072;
    const float* Qg = qkv + base + (size_t)qt * 64 * 3072 + h * 64;

    // stage Q into Ps, then pull A-frags to registers (held across kv loop)
    for (int i = tid; i < 1024; i += 128) {
        int r = i >> 4, c = (i & 15) * 4;
        *(float4*)(Ps + r * 68 + c) = *(const float4*)(Qg + (size_t)r * 3072 + c);
    }
    __syncthreads();
    uint32_t qa[8][4];
    #pragma unroll
    for (int kf = 0; kf < 8; kf++) {
        const float* ap = Ps + (16*warp + g) * 68 + kf*8 + t4;
        qa[kf][0] = __float_as_uint(ap[0]);
        qa[kf][1] = __float_as_uint(ap[8*68]);
        qa[kf][2] = __float_as_uint(ap[4]);
        qa[kf][3] = __float_as_uint(ap[8*68 + 4]);
    }

    float m0 = -INFINITY, m1 = -INFINITY, l0 = 0.f, l1 = 0.f;
    float o[8][4];
    #pragma unroll
    for (int ni = 0; ni < 8; ni++)
        #pragma unroll
        for (int r = 0; r < 4; r++) o[ni][r] = 0.f;

    // prologue: load kv tile 0 into slot 0
    {
        const float* Kg = qkv + base + 1024 + h * 64;
        const float* Vg = qkv + base + 2048 + h * 64;
        for (int i = tid; i < 1024; i += 128) {
            int r = i >> 4, c = (i & 15) * 4;
            CP_ASYNC16(sb + (0*FTILE + r*68 + c)*4, Kg + (size_t)r * 3072 + c);
            CP_ASYNC16(sb + (2*FTILE + r*68 + c)*4, Vg + (size_t)r * 3072 + c);
        }
        CP_COMMIT();
    }

    for (int j = 0; j <= qt; j++) {
        __syncthreads();            // all warps done with previous tile + Ps
        int cur = j & 1;
        if (j + 1 <= qt) {
            int ns = (j + 1) & 1;
            const float* Kg = qkv + base + (size_t)(j+1) * 64 * 3072 + 1024 + h * 64;
            const float* Vg = qkv + base + (size_t)(j+1) * 64 * 3072 + 2048 + h * 64;
            for (int i = tid; i < 1024; i += 128) {
                int r = i >> 4, c = (i & 15) * 4;
                CP_ASYNC16(sb + (ns*FTILE + r*68 + c)*4,       Kg + (size_t)r * 3072 + c);
                CP_ASYNC16(sb + ((2+ns)*FTILE + r*68 + c)*4,   Vg + (size_t)r * 3072 + c);
            }
            CP_COMMIT();
            CP_WAIT1();
        } else {
            CP_WAIT0();
        }
        __syncthreads();            // tile j visible to all
        const float* Ks = fsm + cur * FTILE;
        const float* Vs = fsm + (2 + cur) * FTILE;

        // ---- S = Q K^T ----
        float s[8][4];
        #pragma unroll
        for (int ni = 0; ni < 8; ni++) {
            s[ni][0] = s[ni][1] = s[ni][2] = s[ni][3] = 0.f;
            #pragma unroll
            for (int kf = 0; kf < 8; kf++) {
                const float* bp = Ks + (8*ni + g) * 68 + kf*8 + t4;
                uint32_t bf[2];
                bf[0] = __float_as_uint(bp[0]);
                bf[1] = __float_as_uint(bp[4]);
                mma_tf32_16x8x8(s[ni], qa[kf], bf);
            }
        }

        // scale + causal mask (diag tile)
        int row0 = 16*warp + g, row1 = row0 + 8;
        bool diag = (j == qt);
        #pragma unroll
        for (int ni = 0; ni < 8; ni++) {
            int c0 = 8*ni + 2*t4;
            s[ni][0] *= scale; s[ni][1] *= scale;
            s[ni][2] *= scale; s[ni][3] *= scale;
            if (diag) {
                if (c0     > row0) s[ni][0] = -INFINITY;
                if (c0 + 1 > row0) s[ni][1] = -INFINITY;
                if (c0     > row1) s[ni][2] = -INFINITY;
                if (c0 + 1 > row1) s[ni][3] = -INFINITY;
            }
        }

        // ---- online softmax (row stats in registers; reduce over t4 quad) --
        float mt0 = -INFINITY, mt1 = -INFINITY;
        #pragma unroll
        for (int ni = 0; ni < 8; ni++) {
            mt0 = fmaxf(mt0, fmaxf(s[ni][0], s[ni][1]));
            mt1 = fmaxf(mt1, fmaxf(s[ni][2], s[ni][3]));
        }
        #pragma unroll
        for (int ofs = 1; ofs < 4; ofs <<= 1) {
            mt0 = fmaxf(mt0, __shfl_xor_sync(0xffffffffu, mt0, ofs));
            mt1 = fmaxf(mt1, __shfl_xor_sync(0xffffffffu, mt1, ofs));
        }
        float mn0 = fmaxf(m0, mt0), mn1 = fmaxf(m1, mt1);
        float al0 = __expf(m0 - mn0), al1 = __expf(m1 - mn1);
        float ps0 = 0.f, ps1 = 0.f;
        #pragma unroll
        for (int ni = 0; ni < 8; ni++) {
            s[ni][0] = __expf(s[ni][0] - mn0);
            s[ni][1] = __expf(s[ni][1] - mn0);
            s[ni][2] = __expf(s[ni][2] - mn1);
            s[ni][3] = __expf(s[ni][3] - mn1);
            ps0 += s[ni][0] + s[ni][1];
            ps1 += s[ni][2] + s[ni][3];
        }
        #pragma unroll
        for (int ofs = 1; ofs < 4; ofs <<= 1) {
            ps0 += __shfl_xor_sync(0xffffffffu, ps0, ofs);
            ps1 += __shfl_xor_sync(0xffffffffu, ps1, ofs);
        }
        m0 = mn0; m1 = mn1;
        l0 = l0 * al0 + ps0;
        l1 = l1 * al1 + ps1;
        #pragma unroll
        for (int ni = 0; ni < 8; ni++) {
            o[ni][0] *= al0; o[ni][1] *= al0;
            o[ni][2] *= al1; o[ni][3] *= al1;
        }

        // ---- write P (warp-private rows), re-fragment, O += P V ----
        #pragma unroll
        for (int ni = 0; ni < 8; ni++) {
            *(float2*)(Ps + row0 * 68 + 8*ni + 2*t4) =
                make_float2(rtf32(s[ni][0]), rtf32(s[ni][1]));
            *(float2*)(Ps + row1 * 68 + 8*ni + 2*t4) =
                make_float2(rtf32(s[ni][2]), rtf32(s[ni][3]));
        }
        __syncwarp();
        uint32_t pa[8][4];
        #pragma unroll
        for (int kf = 0; kf < 8; kf++) {
            const float* pp = Ps + (16*warp + g) * 68 + kf*8 + t4;
            pa[kf][0] = __float_as_uint(pp[0]);
            pa[kf][1] = __float_as_uint(pp[8*68]);
            pa[kf][2] = __float_as_uint(pp[4]);
            pa[kf][3] = __float_as_uint(pp[8*68 + 4]);
        }
        #pragma unroll
        for (int ni = 0; ni < 8; ni++) {
            #pragma unroll
            for (int kf = 0; kf < 8; kf++) {
                // B[n=d][k=kv] taken from natural Vs[kv][d]
                const float* vp = Vs + (8*kf + t4) * 68 + 8*ni + g;
                uint32_t bf[2];
                bf[0] = __float_as_uint(vp[0]);
                bf[1] = __float_as_uint(vp[4*68]);
                mma_tf32_16x8x8(o[ni], pa[kf], bf);
            }
        }
    }

    // ---- normalize + store ----
    float inv0 = 1.f / l0, inv1 = 1.f / l1;
    int row0 = 16*warp + g;
    size_t gr0 = (size_t)(b * Nx + qt * 64 + row0) * INNERx + h * 64;
    size_t gr1 = gr0 + (size_t)8 * INNERx;
    #pragma unroll
    for (int ni = 0; ni < 8; ni++) {
        int c = 8*ni + 2*t4;
        *(float2*)(out + gr0 + c) =
            make_float2(rtf32(o[ni][0]*inv0), rtf32(o[ni][1]*inv0));
        *(float2*)(out + gr1 + c) =
            make_float2(rtf32(o[ni][2]*inv1), rtf32(o[ni][3]*inv1));
    }
}

// ---------------- halt ------------------------------------------------------
__global__ __launch_bounds__(256) void halt_k(const float* __restrict__ x2,
                                              const float* __restrict__ w,
                                              const float* __restrict__ b0,
                                              float* __restrict__ out)
{
    int b = blockIdx.x;
    const float* xb = x2 + (size_t)b * Nx * Dx;
    double acc = 0.0;
    for (int i = threadIdx.x; i < Nx * Dx; i += 256)
        acc += (double)xb[i] * (double)w[i & (Dx - 1)];
    __shared__ double sd[256];
    sd[threadIdx.x] = acc;
    __syncthreads();
    for (int s = 128; s > 0; s >>= 1) {
        if (threadIdx.x < s) sd[threadIdx.x] += sd[threadIdx.x + s];
        __syncthreads();
    }
    if (threadIdx.x == 0) out[b] = (float)(sd[0] / (double)Nx) + b0[0];
}

// ---------------- launch ----------------------------------------------------
extern "C" void kernel_launch(void* const* d_in, const int* in_sizes, int n_in,
                              void* d_out, int out_size)
{
    const float* x     = (const float*)d_in[0];
    const float* ln1_g = (const float*)d_in[1];
    const float* ln1_b = (const float*)d_in[2];
    const float* w_qkv = (const float*)d_in[3];
    const float* w_out = (const float*)d_in[4];
    const float* b_out = (const float*)d_in[5];
    const float* ln2_g = (const float*)d_in[6];
    const float* ln2_b = (const float*)d_in[7];
    const float* w_ff1 = (const float*)d_in[8];
    const float* b_ff1 = (const float*)d_in[9];
    const float* w_ff2 = (const float*)d_in[10];
    const float* b_ff2 = (const float*)d_in[11];
    const float* w_hlt = (const float*)d_in[12];
    const float* b_hlt = (const float*)d_in[13];

    float* out_x = (float*)d_out;
    float* out_h = out_x + (size_t)Bx * Nx * Dx;

    void *p_ln, *p_qkv, *p_attn, *p_x1, *p_ff1;
    void *p_wqkvT, *p_woutT, *p_wff1T, *p_wff2T;
    cudaGetSymbolAddress(&p_ln, g_ln);
    cudaGetSymbolAddress(&p_qkv, g_qkv);
    cudaGetSymbolAddress(&p_attn, g_attn);
    cudaGetSymbolAddress(&p_x1, g_x1);
    cudaGetSymbolAddress(&p_ff1, g_ff1);
    cudaGetSymbolAddress(&p_wqkvT, g_wqkvT);
    cudaGetSymbolAddress(&p_woutT, g_woutT);
    cudaGetSymbolAddress(&p_wff1T, g_wff1T);
    cudaGetSymbolAddress(&p_wff2T, g_wff2T);
    float* ln  = (float*)p_ln;
    float* qkv = (float*)p_qkv;
    float* att = (float*)p_attn;
    float* x1  = (float*)p_x1;
    float* ff1 = (float*)p_ff1;

    cudaFuncSetAttribute(flashm_k, cudaFuncAttributeMaxDynamicSharedMemorySize, FLASH_SMEM);
    cudaFuncSetAttribute(mma_gemm<0>, cudaFuncAttributeMaxDynamicSharedMemorySize, GEMM_SMEM);
    cudaFuncSetAttribute(mma_gemm<1>, cudaFuncAttributeMaxDynamicSharedMemorySize, GEMM_SMEM);
    cudaFuncSetAttribute(mma_gemm<2>, cudaFuncAttributeMaxDynamicSharedMemorySize, GEMM_SMEM);

    // 0. weight transposes
    transpose_k<<<dim3(3*INNERx/32, Dx/32), dim3(32, 8)>>>(w_qkv, (float*)p_wqkvT, Dx, 3*INNERx);
    transpose_k<<<dim3(Dx/32, INNERx/32),   dim3(32, 8)>>>(w_out, (float*)p_woutT, INNERx, Dx);
    transpose_k<<<dim3(FFx/32, Dx/32),      dim3(32, 8)>>>(w_ff1, (float*)p_wff1T, Dx, FFx);
    transpose_k<<<dim3(Dx/32, FFx/32),      dim3(32, 8)>>>(w_ff2, (float*)p_wff2T, FFx, Dx);

    // 1. LN1
    ln_k<<<ROWS, 256>>>(x, ln1_g, ln1_b, ln);
    // 2. QKV (rtf32-rounded output feeds attention)
    mma_gemm<0><<<dim3(3*INNERx/256, ROWS/128), 256, GEMM_SMEM>>>(
        ln, (const float*)p_wqkvT, qkv, nullptr, nullptr, ROWS, 3*INNERx, Dx);
    // 3. causal flash attention (tensor cores)
    flashm_k<<<dim3(Nx/64, Bx*Hx), 128, FLASH_SMEM>>>(qkv, att);
    // 4. x1 = att @ w_out + b_out + x
    mma_gemm<1><<<dim3(Dx/256, ROWS/128), 256, GEMM_SMEM>>>(
        att, (const float*)p_woutT, x1, b_out, x, ROWS, Dx, INNERx);
    // 5. LN2
    ln_k<<<ROWS, 256>>>(x1, ln2_g, ln2_b, ln);
    // 6. ff1 = gelu(ln @ w_ff1 + b_ff1)
    mma_gemm<2><<<dim3(FFx/256, ROWS/128), 256, GEMM_SMEM>>>(
        ln, (const float*)p_wff1T, ff1, b_ff1, nullptr, ROWS, FFx, Dx);
    // 7. x2 = ff1 @ w_ff2 + b_ff2 + x1 -> d_out
    mma_gemm<1><<<dim3(Dx/256, ROWS/128), 256, GEMM_SMEM>>>(
        ff1, (const float*)p_wff2T, out_x, b_ff2, x1, ROWS, Dx, FFx);
    // 8. halt
    halt_k<<<Bx, 256>>>(out_x, w_hlt, b_hlt, out_h);
}

// round 5
// speedup vs baseline: 3.4735x; 1.4405x over previous
#include <cuda_runtime.h>
#include <cuda_fp16.h>
#include <math.h>
#include <stdint.h>

#define Bx 4
#define Nx 2048
#define Dx 1024
#define Hx 16
#define DHx 64
#define INNERx 1024
#define FFx 4096
#define ROWS (Bx*Nx)          // 8192

// ---------------- scratch ---------------------------------------------------
__device__ __half g_ln_h  [ROWS*Dx];
__device__ __half g_qkv_h [ROWS*3*INNERx];
__device__ __half g_att_h [ROWS*INNERx];
__device__ float  g_x1    [ROWS*Dx];
__device__ __half g_ff1_h [ROWS*FFx];
__device__ __half g_wqkvT [3*INNERx*Dx];
__device__ __half g_woutT [Dx*INNERx];
__device__ __half g_wff1T [FFx*Dx];
__device__ __half g_wff2T [Dx*FFx];

// ---------------- helpers ---------------------------------------------------
__device__ __forceinline__ uint32_t u32ptr(const void* p) {
    uint32_t a;
    asm("{ .reg .u64 t; cvta.to.shared.u64 t, %1; cvt.u32.u64 %0, t; }"
        : "=r"(a) : "l"(p));
    return a;
}
__device__ __forceinline__ float gelu_exact(float v) {
    return 0.5f * v * (1.0f + erff(v * 0.70710678118654752440f));
}

#define CP_ASYNC16(dst, src) \
    asm volatile("cp.async.cg.shared.global [%0], [%1], 16;" :: "r"(dst), "l"(src))
#define CP_COMMIT() asm volatile("cp.async.commit_group;" ::: "memory")
#define CP_WAIT1()  asm volatile("cp.async.wait_group 1;" ::: "memory")
#define CP_WAIT0()  asm volatile("cp.async.wait_group 0;" ::: "memory")

__device__ __forceinline__ void ldsm_x4(uint32_t* r, uint32_t addr) {
    asm volatile("ldmatrix.sync.aligned.m8n8.x4.shared.b16 {%0,%1,%2,%3}, [%4];"
        : "=r"(r[0]), "=r"(r[1]), "=r"(r[2]), "=r"(r[3]) : "r"(addr));
}
__device__ __forceinline__ void ldsm_x4_t(uint32_t* r, uint32_t addr) {
    asm volatile("ldmatrix.sync.aligned.m8n8.x4.trans.shared.b16 {%0,%1,%2,%3}, [%4];"
        : "=r"(r[0]), "=r"(r[1]), "=r"(r[2]), "=r"(r[3]) : "r"(addr));
}
__device__ __forceinline__ void mma_f16(float* d, const uint32_t* a,
                                        const uint32_t* b) {
    asm volatile(
        "mma.sync.aligned.m16n8k16.row.col.f32.f16.f16.f32 "
        "{%0,%1,%2,%3}, {%4,%5,%6,%7}, {%8,%9}, {%0,%1,%2,%3};"
        : "+f"(d[0]), "+f"(d[1]), "+f"(d[2]), "+f"(d[3])
        : "r"(a[0]), "r"(a[1]), "r"(a[2]), "r"(a[3]), "r"(b[0]), "r"(b[1]));
}

// ---------------- LayerNorm: f32 in, f16 out --------------------------------
__global__ __launch_bounds__(256) void ln_k(const float* __restrict__ x,
                                            const float* __restrict__ g,
                                            const float* __restrict__ b,
                                            __half* __restrict__ y)
{
    int row = blockIdx.x, tid = threadIdx.x;
    const float4* xr = (const float4*)(x + (size_t)row * Dx);
    float4 v = xr[tid];
    float s = v.x + v.y + v.z + v.w;
    float q = v.x*v.x + v.y*v.y + v.z*v.z + v.w*v.w;
    #pragma unroll
    for (int o = 16; o; o >>= 1) {
        s += __shfl_xor_sync(0xffffffffu, s, o);
        q += __shfl_xor_sync(0xffffffffu, q, o);
    }
    __shared__ float ss[8], qs[8];
    if ((tid & 31) == 0) { ss[tid >> 5] = s; qs[tid >> 5] = q; }
    __syncthreads();
    s = 0.f; q = 0.f;
    #pragma unroll
    for (int w = 0; w < 8; w++) { s += ss[w]; q += qs[w]; }
    float mean = s * (1.f / Dx);
    float var  = q * (1.f / Dx) - mean * mean;
    float inv  = rsqrtf(var + 1e-5f);
    float4 gv = ((const float4*)g)[tid];
    float4 bv = ((const float4*)b)[tid];
    __half2 h0 = __floats2half2_rn((v.x - mean) * inv * gv.x + bv.x,
                                   (v.y - mean) * inv * gv.y + bv.y);
    __half2 h1 = __floats2half2_rn((v.z - mean) * inv * gv.z + bv.z,
                                   (v.w - mean) * inv * gv.w + bv.w);
    uint2 pk = make_uint2(*(uint32_t*)&h0, *(uint32_t*)&h1);
    *(uint2*)(y + (size_t)row * Dx + tid * 4) = pk;
}

// ---------------- weight transpose W[K][N] -> WT[N][K] in f16 ---------------
__global__ __launch_bounds__(256) void transpose_k(const float* __restrict__ W,
                                                   __half* __restrict__ WT,
                                                   int K, int N)
{
    __shared__ float t[32][33];
    int n0 = blockIdx.x * 32, k0 = blockIdx.y * 32;
    int tx = threadIdx.x, ty = threadIdx.y;
    #pragma unroll
    for (int i = ty; i < 32; i += 8)
        t[i][tx] = W[(size_t)(k0 + i) * N + n0 + tx];
    __syncthreads();
    #pragma unroll
    for (int i = ty; i < 32; i += 8)
        WT[(size_t)(n0 + i) * K + k0 + tx] = __float2half(t[tx][i]);
}

// ---------------- fp16 mma GEMM: 128x256 CTA, 8 warps of 64x64 --------------
// A[M][K] f16 row-major, BT[N][K] f16 row-major, K-chunk 64, 3 stages.
#define SA 72                                 // smem row stride (halves)
#define A_ST (128*SA)                         // halves
#define B_ST (256*SA)
#define STG  (A_ST + B_ST)                    // 27648 halves = 55296 B
#define GEMM_SMEM (3*STG*2)                   // 165888 B

template<int EPI>  // 0: half out; 1: f32 out +bias+res; 2: half out gelu(+bias)
__global__ __launch_bounds__(256) void hgemm(
    const __half* __restrict__ A, const __half* __restrict__ BT,
    void* __restrict__ Cv, const float* __restrict__ bias,
    const float* __restrict__ res, int M, int N, int K)
{
    extern __shared__ __half hsm[];
    int tid = threadIdx.x, lane = tid & 31, warp = tid >> 5;
    int bm = blockIdx.y * 128, bn = blockIdx.x * 256;
    int wm = (warp >> 2) * 64, wn = (warp & 3) * 64;
    int g = lane >> 2, t4 = lane & 3;
    int lrow = lane & 15, lk = (lane >> 4) << 3;          // A/P frag lane addr
    int brow = (lane & 7) + ((lane & 16) >> 1);           // B frag lane addr
    int bk = lane & 8;

    float acc[4][8][4];
    #pragma unroll
    for (int mi = 0; mi < 4; mi++)
        #pragma unroll
        for (int ni = 0; ni < 8; ni++)
            #pragma unroll
            for (int r = 0; r < 4; r++) acc[mi][ni][r] = 0.f;

    uint32_t sb = u32ptr(hsm);
    int arow = tid >> 3, ac8 = (tid & 7) * 8;
    int nK = K >> 6;

    // prologue: chunks 0,1
    #pragma unroll
    for (int s = 0; s < 2; s++) {
        int kt = s * 64;
        #pragma unroll
        for (int it = 0; it < 4; it++) {
            int row = arow + it * 32;
            CP_ASYNC16(sb + (s*STG + row*SA + ac8)*2,
                       A + (size_t)(bm + row) * K + kt + ac8);
        }
        #pragma unroll
        for (int it = 0; it < 8; it++) {
            int row = arow + it * 32;
            CP_ASYNC16(sb + (s*STG + A_ST + row*SA + ac8)*2,
                       BT + (size_t)(bn + row) * K + kt + ac8);
        }
        CP_COMMIT();
    }

    for (int i = 0; i < nK; i++) {
        int slot = i % 3;
        if (i + 2 < nK) CP_WAIT1(); else CP_WAIT0();
        __syncthreads();

        int nx = i + 2;
        if (nx < nK) {
            int ns = nx % 3, kt = nx * 64;
            #pragma unroll
            for (int it = 0; it < 4; it++) {
                int row = arow + it * 32;
                CP_ASYNC16(sb + (ns*STG + row*SA + ac8)*2,
                           A + (size_t)(bm + row) * K + kt + ac8);
            }
            #pragma unroll
            for (int it = 0; it < 8; it++) {
                int row = arow + it * 32;
                CP_ASYNC16(sb + (ns*STG + A_ST + row*SA + ac8)*2,
                           BT + (size_t)(bn + row) * K + kt + ac8);
            }
            CP_COMMIT();
        }

        uint32_t sA = sb + slot * STG * 2;
        uint32_t sB = sA + A_ST * 2;
        #pragma unroll
        for (int ks = 0; ks < 4; ks++) {
            int k = ks * 16;
            uint32_t af[4][4], bq[4][4];
            #pragma unroll
            for (int mi = 0; mi < 4; mi++)
                ldsm_x4(af[mi], sA + ((wm + 16*mi + lrow)*SA + k + lk)*2);
            #pragma unroll
            for (int p = 0; p < 4; p++)
                ldsm_x4(bq[p], sB + ((wn + 16*p + brow)*SA + k + bk)*2);
            #pragma unroll
            for (int mi = 0; mi < 4; mi++)
                #pragma unroll
                for (int p = 0; p < 4; p++) {
                    mma_f16(acc[mi][2*p],     af[mi], &bq[p][0]);
                    mma_f16(acc[mi][2*p + 1], af[mi], &bq[p][2]);
                }
        }
    }

    // epilogue
    #pragma unroll
    for (int mi = 0; mi < 4; mi++) {
        #pragma unroll
        for (int ni = 0; ni < 8; ni++) {
            int col = bn + wn + 8*ni + 2*t4;
            #pragma unroll
            for (int h = 0; h < 2; h++) {
                int row = bm + wm + 16*mi + g + 8*h;
                float v0 = acc[mi][ni][2*h + 0];
                float v1 = acc[mi][ni][2*h + 1];
                if (EPI == 0) {
                    *(__half2*)((__half*)Cv + (size_t)row * N + col) =
                        __floats2half2_rn(v0, v1);
                } else if (EPI == 1) {
                    v0 += bias[col]; v1 += bias[col + 1];
                    float2 rr = *(const float2*)(res + (size_t)row * N + col);
                    *(float2*)((float*)Cv + (size_t)row * N + col) =
                        make_float2(v0 + rr.x, v1 + rr.y);
                } else {
                    v0 = gelu_exact(v0 + bias[col]);
                    v1 = gelu_exact(v1 + bias[col + 1]);
                    *(__half2*)((__half*)Cv + (size_t)row * N + col) =
                        __floats2half2_rn(v0, v1);
                }
            }
        }
    }
}

// ---------------- fp16 flash attention: 64-q tile, 4 warps ------------------
// smem halves: K0 @0, K1 @4608, V0 @9216, V1 @13824, Ps @18432 (stride 72)
#define FT (64*SA)                            // 4608 halves per tile
#define FLASH_SMEM (5*FT*2)                   // 46080 B

__global__ __launch_bounds__(128) void flashh_k(const __half* __restrict__ qkv,
                                                __half* __restrict__ out)
{
    extern __shared__ __half fsm[];
    __half* Ps = fsm + 4 * FT;
    uint32_t sb = u32ptr(fsm);
    uint32_t sP = sb + 4 * FT * 2;

    int qt = blockIdx.x, bh = blockIdx.y;
    int b = bh >> 4, h = bh & 15;
    int tid = threadIdx.x, lane = tid & 31, warp = tid >> 5;
    int g = lane >> 2, t4 = lane & 3;
    int lrow = lane & 15, lk = (lane >> 4) << 3;
    int brow = (lane & 7) + ((lane & 16) >> 1);
    int bk = lane & 8;
    const float scale = 0.125f;

    size_t base = (size_t)b * Nx * 3072;
    const __half* Qg = qkv + base + (size_t)qt * 64 * 3072 + h * 64;

    // stage Q into Ps via cp.async, then KV tile 0
    {
        int r = tid >> 1, c8 = (tid & 1) * 8;   // 64 rows x 2 chunks... need 8
        // 64 rows * 8 chunks = 512; 128 threads -> 4 each
        for (int it = 0; it < 4; it++) {
            int id = tid + it * 128;
            int rr = id >> 3, cc = (id & 7) * 8;
            CP_ASYNC16(sP + (rr*SA + cc)*2, Qg + (size_t)rr * 3072 + cc);
        }
        (void)r; (void)c8;
        CP_COMMIT();
        const __half* Kg = qkv + base + 1024 + h * 64;
        const __half* Vg = qkv + base + 2048 + h * 64;
        for (int it = 0; it < 4; it++) {
            int id = tid + it * 128;
            int rr = id >> 3, cc = (id & 7) * 8;
            CP_ASYNC16(sb + (0*FT + rr*SA + cc)*2, Kg + (size_t)rr * 3072 + cc);
            CP_ASYNC16(sb + (2*FT + rr*SA + cc)*2, Vg + (size_t)rr * 3072 + cc);
        }
        CP_COMMIT();
        CP_WAIT1();               // Q arrived
        __syncthreads();
    }

    uint32_t qa[4][4];
    #pragma unroll
    for (int kf = 0; kf < 4; kf++)
        ldsm_x4(qa[kf], sP + ((16*warp + lrow)*SA + 16*kf + lk)*2);

    float m0 = -INFINITY, m1 = -INFINITY, l0 = 0.f, l1 = 0.f;
    float o[8][4];
    #pragma unroll
    for (int ni = 0; ni < 8; ni++)
        #pragma unroll
        for (int r = 0; r < 4; r++) o[ni][r] = 0.f;

    for (int j = 0; j <= qt; j++) {
        __syncthreads();           // prev tile + Ps free, qa loaded
        int cur = j & 1;
        if (j + 1 <= qt) {
            int ns = (j + 1) & 1;
            const __half* Kg = qkv + base + (size_t)(j+1) * 64 * 3072 + 1024 + h * 64;
            const __half* Vg = qkv + base + (size_t)(j+1) * 64 * 3072 + 2048 + h * 64;
            #pragma unroll
            for (int it = 0; it < 4; it++) {
                int id = tid + it * 128;
                int rr = id >> 3, cc = (id & 7) * 8;
                CP_ASYNC16(sb + (ns*FT + rr*SA + cc)*2,     Kg + (size_t)rr * 3072 + cc);
                CP_ASYNC16(sb + ((2+ns)*FT + rr*SA + cc)*2, Vg + (size_t)rr * 3072 + cc);
            }
            CP_COMMIT();
            CP_WAIT1();
        } else {
            CP_WAIT0();
        }
        __syncthreads();
        uint32_t sK = sb + cur * FT * 2;
        uint32_t sV = sb + (2 + cur) * FT * 2;

        // ---- S = Q K^T ----
        float s[8][4];
        #pragma unroll
        for (int ni = 0; ni < 8; ni++)
            s[ni][0] = s[ni][1] = s[ni][2] = s[ni][3] = 0.f;
        #pragma unroll
        for (int kf = 0; kf < 4; kf++) {
            uint32_t bq[4][4];
            #pragma unroll
            for (int p = 0; p < 4; p++)
                ldsm_x4(bq[p], sK + ((16*p + brow)*SA + 16*kf + bk)*2);
            #pragma unroll
            for (int p = 0; p < 4; p++) {
                mma_f16(s[2*p],     qa[kf], &bq[p][0]);
                mma_f16(s[2*p + 1], qa[kf], &bq[p][2]);
            }
        }

        // scale + causal mask
        int row0 = 16*warp + g, row1 = row0 + 8;
        bool diag = (j == qt);
        #pragma unroll
        for (int ni = 0; ni < 8; ni++) {
            int c0 = 8*ni + 2*t4;
            s[ni][0] *= scale; s[ni][1] *= scale;
            s[ni][2] *= scale; s[ni][3] *= scale;
            if (diag) {
                if (c0     > row0) s[ni][0] = -INFINITY;
                if (c0 + 1 > row0) s[ni][1] = -INFINITY;
                if (c0     > row1) s[ni][2] = -INFINITY;
                if (c0 + 1 > row1) s[ni][3] = -INFINITY;
            }
        }

        // ---- online softmax ----
        float mt0 = -INFINITY, mt1 = -INFINITY;
        #pragma unroll
        for (int ni = 0; ni < 8; ni++) {
            mt0 = fmaxf(mt0, fmaxf(s[ni][0], s[ni][1]));
            mt1 = fmaxf(mt1, fmaxf(s[ni][2], s[ni][3]));
        }
        #pragma unroll
        for (int ofs = 1; ofs < 4; ofs <<= 1) {
            mt0 = fmaxf(mt0, __shfl_xor_sync(0xffffffffu, mt0, ofs));
            mt1 = fmaxf(mt1, __shfl_xor_sync(0xffffffffu, mt1, ofs));
        }
        float mn0 = fmaxf(m0, mt0), mn1 = fmaxf(m1, mt1);
        float al0 = __expf(m0 - mn0), al1 = __expf(m1 - mn1);
        float ps0 = 0.f, ps1 = 0.f;
        #pragma unroll
        for (int ni = 0; ni < 8; ni++) {
            s[ni][0] = __expf(s[ni][0] - mn0);
            s[ni][1] = __expf(s[ni][1] - mn0);
            s[ni][2] = __expf(s[ni][2] - mn1);
            s[ni][3] = __expf(s[ni][3] - mn1);
            ps0 += s[ni][0] + s[ni][1];
            ps1 += s[ni][2] + s[ni][3];
        }
        #pragma unroll
        for (int ofs = 1; ofs < 4; ofs <<= 1) {
            ps0 += __shfl_xor_sync(0xffffffffu, ps0, ofs);
            ps1 += __shfl_xor_sync(0xffffffffu, ps1, ofs);
        }
        m0 = mn0; m1 = mn1;
        l0 = l0 * al0 + ps0;
        l1 = l1 * al1 + ps1;
        #pragma unroll
        for (int ni = 0; ni < 8; ni++) {
            o[ni][0] *= al0; o[ni][1] *= al0;
            o[ni][2] *= al1; o[ni][3] *= al1;
        }

        // ---- P -> half smem (warp-private rows), re-fragment, O += P V ----
        #pragma unroll
        for (int ni = 0; ni < 8; ni++) {
            *(__half2*)(Ps + row0*SA + 8*ni + 2*t4) = __floats2half2_rn(s[ni][0], s[ni][1]);
            *(__half2*)(Ps + row1*SA + 8*ni + 2*t4) = __floats2half2_rn(s[ni][2], s[ni][3]);
        }
        __syncwarp();
        uint32_t pa[4][4];
        #pragma unroll
        for (int kf = 0; kf < 4; kf++)
            ldsm_x4(pa[kf], sP + ((16*warp + lrow)*SA + 16*kf + lk)*2);
        #pragma unroll
        for (int kf = 0; kf < 4; kf++) {
            uint32_t vq[4][4];
            #pragma unroll
            for (int p = 0; p < 4; p++)
                ldsm_x4_t(vq[p], sV + ((16*kf + lrow)*SA + 16*p + lk)*2);
            #pragma unroll
            for (int p = 0; p < 4; p++) {
                mma_f16(o[2*p],     pa[kf], &vq[p][0]);
                mma_f16(o[2*p + 1], pa[kf], &vq[p][2]);
            }
        }
    }

    // ---- normalize + store (half) ----
    float inv0 = 1.f / l0, inv1 = 1.f / l1;
    int row0 = 16*warp + g;
    size_t gr0 = (size_t)(b * Nx + qt * 64 + row0) * INNERx + h * 64;
    size_t gr1 = gr0 + (size_t)8 * INNERx;
    #pragma unroll
    for (int ni = 0; ni < 8; ni++) {
        int c = 8*ni + 2*t4;
        *(__half2*)(out + gr0 + c) = __floats2half2_rn(o[ni][0]*inv0, o[ni][1]*inv0);
        *(__half2*)(out + gr1 + c) = __floats2half2_rn(o[ni][2]*inv1, o[ni][3]*inv1);
    }
}

// ---------------- halt ------------------------------------------------------
__global__ __launch_bounds__(256) void halt_k(const float* __restrict__ x2,
                                              const float* __restrict__ w,
                                              const float* __restrict__ b0,
                                              float* __restrict__ out)
{
    int b = blockIdx.x;
    const float* xb = x2 + (size_t)b * Nx * Dx;
    double acc = 0.0;
    for (int i = threadIdx.x; i < Nx * Dx; i += 256)
        acc += (double)xb[i] * (double)w[i & (Dx - 1)];
    __shared__ double sd[256];
    sd[threadIdx.x] = acc;
    __syncthreads();
    for (int s = 128; s > 0; s >>= 1) {
        if (threadIdx.x < s) sd[threadIdx.x] += sd[threadIdx.x + s];
        __syncthreads();
    }
    if (threadIdx.x == 0) out[b] = (float)(sd[0] / (double)Nx) + b0[0];
}

// ---------------- launch ----------------------------------------------------
extern "C" void kernel_launch(void* const* d_in, const int* in_sizes, int n_in,
                              void* d_out, int out_size)
{
    const float* x     = (const float*)d_in[0];
    const float* ln1_g = (const float*)d_in[1];
    const float* ln1_b = (const float*)d_in[2];
    const float* w_qkv = (const float*)d_in[3];
    const float* w_out = (const float*)d_in[4];
    const float* b_out = (const float*)d_in[5];
    const float* ln2_g = (const float*)d_in[6];
    const float* ln2_b = (const float*)d_in[7];
    const float* w_ff1 = (const float*)d_in[8];
    const float* b_ff1 = (const float*)d_in[9];
    const float* w_ff2 = (const float*)d_in[10];
    const float* b_ff2 = (const float*)d_in[11];
    const float* w_hlt = (const float*)d_in[12];
    const float* b_hlt = (const float*)d_in[13];

    float* out_x = (float*)d_out;
    float* out_h = out_x + (size_t)Bx * Nx * Dx;

    void *p_ln, *p_qkv, *p_att, *p_x1, *p_ff1;
    void *p_wqkvT, *p_woutT, *p_wff1T, *p_wff2T;
    cudaGetSymbolAddress(&p_ln, g_ln_h);
    cudaGetSymbolAddress(&p_qkv, g_qkv_h);
    cudaGetSymbolAddress(&p_att, g_att_h);
    cudaGetSymbolAddress(&p_x1, g_x1);
    cudaGetSymbolAddress(&p_ff1, g_ff1_h);
    cudaGetSymbolAddress(&p_wqkvT, g_wqkvT);
    cudaGetSymbolAddress(&p_woutT, g_woutT);
    cudaGetSymbolAddress(&p_wff1T, g_wff1T);
    cudaGetSymbolAddress(&p_wff2T, g_wff2T);
    __half* ln  = (__half*)p_ln;
    __half* qkv = (__half*)p_qkv;
    __half* att = (__half*)p_att;
    float*  x1  = (float*)p_x1;
    __half* ff1 = (__half*)p_ff1;

    cudaFuncSetAttribute(flashh_k, cudaFuncAttributeMaxDynamicSharedMemorySize, FLASH_SMEM);
    cudaFuncSetAttribute(hgemm<0>, cudaFuncAttributeMaxDynamicSharedMemorySize, GEMM_SMEM);
    cudaFuncSetAttribute(hgemm<1>, cudaFuncAttributeMaxDynamicSharedMemorySize, GEMM_SMEM);
    cudaFuncSetAttribute(hgemm<2>, cudaFuncAttributeMaxDynamicSharedMemorySize, GEMM_SMEM);

    // 0. weight transposes -> f16 K-major
    transpose_k<<<dim3(3*INNERx/32, Dx/32), dim3(32, 8)>>>(w_qkv, (__half*)p_wqkvT, Dx, 3*INNERx);
    transpose_k<<<dim3(Dx/32, INNERx/32),   dim3(32, 8)>>>(w_out, (__half*)p_woutT, INNERx, Dx);
    transpose_k<<<dim3(FFx/32, Dx/32),      dim3(32, 8)>>>(w_ff1, (__half*)p_wff1T, Dx, FFx);
    transpose_k<<<dim3(Dx/32, FFx/32),      dim3(32, 8)>>>(w_ff2, (__half*)p_wff2T, FFx, Dx);

    // 1. LN1 -> f16
    ln_k<<<ROWS, 256>>>(x, ln1_g, ln1_b, ln);
    // 2. QKV (f16 out)
    hgemm<0><<<dim3(3*INNERx/256, ROWS/128), 256, GEMM_SMEM>>>(
        ln, (const __half*)p_wqkvT, qkv, nullptr, nullptr, ROWS, 3*INNERx, Dx);
    // 3. causal flash attention (f16 tensor cores)
    flashh_k<<<dim3(Nx/64, Bx*Hx), 128, FLASH_SMEM>>>(qkv, att);
    // 4. x1 = att @ w_out + b_out + x  (f32 out)
    hgemm<1><<<dim3(Dx/256, ROWS/128), 256, GEMM_SMEM>>>(
        att, (const __half*)p_woutT, x1, b_out, x, ROWS, Dx, INNERx);
    // 5. LN2 -> f16
    ln_k<<<ROWS, 256>>>(x1, ln2_g, ln2_b, ln);
    // 6. ff1 = gelu(ln @ w_ff1 + b_ff1)  (f16 out)
    hgemm<2><<<dim3(FFx/256, ROWS/128), 256, GEMM_SMEM>>>(
        ln, (const __half*)p_wff1T, ff1, b_ff1, nullptr, ROWS, FFx, Dx);
    // 7. x2 = ff1 @ w_ff2 + b_ff2 + x1 -> d_out (f32)
    hgemm<1><<<dim3(Dx/256, ROWS/128), 256, GEMM_SMEM>>>(
        ff1, (const __half*)p_wff2T, out_x, b_ff2, x1, ROWS, Dx, FFx);
    // 8. halt
    halt_k<<<Bx, 256>>>(out_x, w_hlt, b_hlt, out_h);
}

// round 6
// speedup vs baseline: 7.4165x; 2.1351x over previous
#include <cuda_runtime.h>
#include <cuda_fp16.h>
#include <math.h>
#include <stdint.h>

#define Bx 4
#define Nx 2048
#define Dx 1024
#define Hx 16
#define DHx 64
#define INNERx 1024
#define FFx 4096
#define ROWS (Bx*Nx)          // 8192

// ---------------- scratch ---------------------------------------------------
__device__ __half g_ln_h  [ROWS*Dx];
__device__ __half g_qkv_h [ROWS*3*INNERx];
__device__ __half g_att_h [ROWS*INNERx];
__device__ float  g_x1    [ROWS*Dx];
__device__ __half g_ff1_h [ROWS*FFx];
__device__ __half g_wqkvT [3*INNERx*Dx];
__device__ __half g_woutT [Dx*INNERx];
__device__ __half g_wff1T [FFx*Dx];
__device__ __half g_wff2T [Dx*FFx];
__device__ double g_hp    [256];

// ---------------- helpers ---------------------------------------------------
__device__ __forceinline__ uint32_t u32ptr(const void* p) {
    uint32_t a;
    asm("{ .reg .u64 t; cvta.to.shared.u64 t, %1; cvt.u32.u64 %0, t; }"
        : "=r"(a) : "l"(p));
    return a;
}
__device__ __forceinline__ float gelu_exact(float v) {
    return 0.5f * v * (1.0f + erff(v * 0.70710678118654752440f));
}

#define CP_ASYNC16(dst, src) \
    asm volatile("cp.async.cg.shared.global [%0], [%1], 16;" :: "r"(dst), "l"(src))
#define CP_COMMIT() asm volatile("cp.async.commit_group;" ::: "memory")
#define CP_WAIT1()  asm volatile("cp.async.wait_group 1;" ::: "memory")
#define CP_WAIT0()  asm volatile("cp.async.wait_group 0;" ::: "memory")

__device__ __forceinline__ void ldsm_x4(uint32_t* r, uint32_t addr) {
    asm volatile("ldmatrix.sync.aligned.m8n8.x4.shared.b16 {%0,%1,%2,%3}, [%4];"
        : "=r"(r[0]), "=r"(r[1]), "=r"(r[2]), "=r"(r[3]) : "r"(addr));
}
__device__ __forceinline__ void ldsm_x4_t(uint32_t* r, uint32_t addr) {
    asm volatile("ldmatrix.sync.aligned.m8n8.x4.trans.shared.b16 {%0,%1,%2,%3}, [%4];"
        : "=r"(r[0]), "=r"(r[1]), "=r"(r[2]), "=r"(r[3]) : "r"(addr));
}
__device__ __forceinline__ void mma_f16(float* d, const uint32_t* a,
                                        const uint32_t* b) {
    asm volatile(
        "mma.sync.aligned.m16n8k16.row.col.f32.f16.f16.f32 "
        "{%0,%1,%2,%3}, {%4,%5,%6,%7}, {%8,%9}, {%0,%1,%2,%3};"
        : "+f"(d[0]), "+f"(d[1]), "+f"(d[2]), "+f"(d[3])
        : "r"(a[0]), "r"(a[1]), "r"(a[2]), "r"(a[3]), "r"(b[0]), "r"(b[1]));
}

// ---------------- LayerNorm: f32 in, f16 out --------------------------------
__global__ __launch_bounds__(256) void ln_k(const float* __restrict__ x,
                                            const float* __restrict__ g,
                                            const float* __restrict__ b,
                                            __half* __restrict__ y)
{
    int row = blockIdx.x, tid = threadIdx.x;
    const float4* xr = (const float4*)(x + (size_t)row * Dx);
    float4 v = xr[tid];
    float s = v.x + v.y + v.z + v.w;
    float q = v.x*v.x + v.y*v.y + v.z*v.z + v.w*v.w;
    #pragma unroll
    for (int o = 16; o; o >>= 1) {
        s += __shfl_xor_sync(0xffffffffu, s, o);
        q += __shfl_xor_sync(0xffffffffu, q, o);
    }
    __shared__ float ss[8], qs[8];
    if ((tid & 31) == 0) { ss[tid >> 5] = s; qs[tid >> 5] = q; }
    __syncthreads();
    s = 0.f; q = 0.f;
    #pragma unroll
    for (int w = 0; w < 8; w++) { s += ss[w]; q += qs[w]; }
    float mean = s * (1.f / Dx);
    float var  = q * (1.f / Dx) - mean * mean;
    float inv  = rsqrtf(var + 1e-5f);
    float4 gv = ((const float4*)g)[tid];
    float4 bv = ((const float4*)b)[tid];
    __half2 h0 = __floats2half2_rn((v.x - mean) * inv * gv.x + bv.x,
                                   (v.y - mean) * inv * gv.y + bv.y);
    __half2 h1 = __floats2half2_rn((v.z - mean) * inv * gv.z + bv.z,
                                   (v.w - mean) * inv * gv.w + bv.w);
    uint2 pk = make_uint2(*(uint32_t*)&h0, *(uint32_t*)&h1);
    *(uint2*)(y + (size_t)row * Dx + tid * 4) = pk;
}

// ---------------- weight transpose W[K][N] -> WT[N][K] in f16 ---------------
__global__ __launch_bounds__(256) void transpose_k(const float* __restrict__ W,
                                                   __half* __restrict__ WT,
                                                   int K, int N)
{
    __shared__ float t[32][33];
    int n0 = blockIdx.x * 32, k0 = blockIdx.y * 32;
    int tx = threadIdx.x, ty = threadIdx.y;
    #pragma unroll
    for (int i = ty; i < 32; i += 8)
        t[i][tx] = W[(size_t)(k0 + i) * N + n0 + tx];
    __syncthreads();
    #pragma unroll
    for (int i = ty; i < 32; i += 8)
        WT[(size_t)(n0 + i) * K + k0 + tx] = __float2half(t[tx][i]);
}

// ---------------- fp16 mma GEMM: 128x256 CTA, 8 warps of 64x64, 2 stages ----
#define SA 72
#define A_ST (128*SA)
#define B_ST (256*SA)
#define STG  (A_ST + B_ST)                    // 27648 halves = 55296 B
#define GEMM_SMEM (2*STG*2)                   // 110592 B -> 2 CTAs/SM

template<int EPI>  // 0: half out; 1: f32 out +bias+res; 2: half out gelu(+bias)
__global__ __launch_bounds__(256) void hgemm(
    const __half* __restrict__ A, const __half* __restrict__ BT,
    void* __restrict__ Cv, const float* __restrict__ bias,
    const float* __restrict__ res, int M, int N, int K)
{
    extern __shared__ __half hsm[];
    int tid = threadIdx.x, lane = tid & 31, warp = tid >> 5;
    int bm = blockIdx.y * 128, bn = blockIdx.x * 256;
    int wm = (warp >> 2) * 64, wn = (warp & 3) * 64;
    int g = lane >> 2, t4 = lane & 3;
    int lrow = lane & 15, lk = (lane >> 4) << 3;
    int brow = (lane & 7) + ((lane & 16) >> 1);
    int bk = lane & 8;

    float acc[4][8][4];
    #pragma unroll
    for (int mi = 0; mi < 4; mi++)
        #pragma unroll
        for (int ni = 0; ni < 8; ni++)
            #pragma unroll
            for (int r = 0; r < 4; r++) acc[mi][ni][r] = 0.f;

    uint32_t sb = u32ptr(hsm);
    int arow = tid >> 3, ac8 = (tid & 7) * 8;
    int nK = K >> 6;

    // prologue: chunk 0 into slot 0
    #pragma unroll
    for (int it = 0; it < 4; it++) {
        int row = arow + it * 32;
        CP_ASYNC16(sb + (row*SA + ac8)*2, A + (size_t)(bm + row) * K + ac8);
    }
    #pragma unroll
    for (int it = 0; it < 8; it++) {
        int row = arow + it * 32;
        CP_ASYNC16(sb + (A_ST + row*SA + ac8)*2, BT + (size_t)(bn + row) * K + ac8);
    }
    CP_COMMIT();

    for (int i = 0; i < nK; i++) {
        CP_WAIT0();
        __syncthreads();

        int nx = i + 1;
        if (nx < nK) {
            int ns = nx & 1, kt = nx * 64;
            #pragma unroll
            for (int it = 0; it < 4; it++) {
                int row = arow + it * 32;
                CP_ASYNC16(sb + (ns*STG + row*SA + ac8)*2,
                           A + (size_t)(bm + row) * K + kt + ac8);
            }
            #pragma unroll
            for (int it = 0; it < 8; it++) {
                int row = arow + it * 32;
                CP_ASYNC16(sb + (ns*STG + A_ST + row*SA + ac8)*2,
                           BT + (size_t)(bn + row) * K + kt + ac8);
            }
            CP_COMMIT();
        }

        uint32_t sA = sb + (i & 1) * STG * 2;
        uint32_t sB = sA + A_ST * 2;
        #pragma unroll
        for (int ks = 0; ks < 4; ks++) {
            int k = ks * 16;
            uint32_t af[4][4], bq[4][4];
            #pragma unroll
            for (int mi = 0; mi < 4; mi++)
                ldsm_x4(af[mi], sA + ((wm + 16*mi + lrow)*SA + k + lk)*2);
            #pragma unroll
            for (int p = 0; p < 4; p++)
                ldsm_x4(bq[p], sB + ((wn + 16*p + brow)*SA + k + bk)*2);
            #pragma unroll
            for (int mi = 0; mi < 4; mi++)
                #pragma unroll
                for (int p = 0; p < 4; p++) {
                    mma_f16(acc[mi][2*p],     af[mi], &bq[p][0]);
                    mma_f16(acc[mi][2*p + 1], af[mi], &bq[p][2]);
                }
        }
    }

    // epilogue
    #pragma unroll
    for (int mi = 0; mi < 4; mi++) {
        #pragma unroll
        for (int ni = 0; ni < 8; ni++) {
            int col = bn + wn + 8*ni + 2*t4;
            #pragma unroll
            for (int h = 0; h < 2; h++) {
                int row = bm + wm + 16*mi + g + 8*h;
                float v0 = acc[mi][ni][2*h + 0];
                float v1 = acc[mi][ni][2*h + 1];
                if (EPI == 0) {
                    *(__half2*)((__half*)Cv + (size_t)row * N + col) =
                        __floats2half2_rn(v0, v1);
                } else if (EPI == 1) {
                    v0 += bias[col]; v1 += bias[col + 1];
                    float2 rr = *(const float2*)(res + (size_t)row * N + col);
                    *(float2*)((float*)Cv + (size_t)row * N + col) =
                        make_float2(v0 + rr.x, v1 + rr.y);
                } else {
                    v0 = gelu_exact(v0 + bias[col]);
                    v1 = gelu_exact(v1 + bias[col + 1]);
                    *(__half2*)((__half*)Cv + (size_t)row * N + col) =
                        __floats2half2_rn(v0, v1);
                }
            }
        }
    }
}

// ---------------- fp16 flash attention: 128-q tile, 8 warps -----------------
// smem halves: K0 @0, K1, V0, V1 (each 64*72), Ps/Q @4*64*72 (128*72)
#define FSA 72
#define FKV (64*FSA)
#define FLASH_SMEM ((4*FKV + 128*FSA)*2)     // 55296 B

__global__ __launch_bounds__(256) void flashh_k(const __half* __restrict__ qkv,
                                                __half* __restrict__ out)
{
    extern __shared__ __half fsm[];
    __half* Ps = fsm + 4 * FKV;
    uint32_t sb = u32ptr(fsm);
    uint32_t sP = sb + 4 * FKV * 2;

    int qt = blockIdx.x, bh = blockIdx.y;          // qt: 0..15 (128-row tiles)
    int b = bh >> 4, h = bh & 15;
    int tid = threadIdx.x, lane = tid & 31, warp = tid >> 5;
    int g = lane >> 2, t4 = lane & 3;
    int lrow = lane & 15, lk = (lane >> 4) << 3;
    int brow = (lane & 7) + ((lane & 16) >> 1);
    int bk = lane & 8;
    const float scale = 0.125f;

    size_t base = (size_t)b * Nx * 3072;
    const __half* Qg = qkv + base + (size_t)qt * 128 * 3072 + h * 64;
    int jmax = 2 * qt + 1;

    // stage Q (128x64) into Ps, KV tile 0
    {
        #pragma unroll
        for (int it = 0; it < 4; it++) {
            int id = tid + it * 256;
            int rr = id >> 3, cc = (id & 7) * 8;
            CP_ASYNC16(sP + (rr*FSA + cc)*2, Qg + (size_t)rr * 3072 + cc);
        }
        CP_COMMIT();
        const __half* Kg = qkv + base + 1024 + h * 64;
        const __half* Vg = qkv + base + 2048 + h * 64;
        #pragma unroll
        for (int it = 0; it < 2; it++) {
            int id = tid + it * 256;
            int rr = id >> 3, cc = (id & 7) * 8;
            CP_ASYNC16(sb + (0*FKV + rr*FSA + cc)*2, Kg + (size_t)rr * 3072 + cc);
            CP_ASYNC16(sb + (2*FKV + rr*FSA + cc)*2, Vg + (size_t)rr * 3072 + cc);
        }
        CP_COMMIT();
        CP_WAIT1();
        __syncthreads();
    }

    uint32_t qa[4][4];
    #pragma unroll
    for (int kf = 0; kf < 4; kf++)
        ldsm_x4(qa[kf], sP + ((16*warp + lrow)*FSA + 16*kf + lk)*2);

    float m0 = -INFINITY, m1 = -INFINITY, l0 = 0.f, l1 = 0.f;
    float o[8][4];
    #pragma unroll
    for (int ni = 0; ni < 8; ni++)
        #pragma unroll
        for (int r = 0; r < 4; r++) o[ni][r] = 0.f;

    for (int j = 0; j <= jmax; j++) {
        __syncthreads();
        int cur = j & 1;
        if (j + 1 <= jmax) {
            int ns = (j + 1) & 1;
            const __half* Kg = qkv + base + (size_t)(j+1) * 64 * 3072 + 1024 + h * 64;
            const __half* Vg = qkv + base + (size_t)(j+1) * 64 * 3072 + 2048 + h * 64;
            #pragma unroll
            for (int it = 0; it < 2; it++) {
                int id = tid + it * 256;
                int rr = id >> 3, cc = (id & 7) * 8;
                CP_ASYNC16(sb + (ns*FKV + rr*FSA + cc)*2,     Kg + (size_t)rr * 3072 + cc);
                CP_ASYNC16(sb + ((2+ns)*FKV + rr*FSA + cc)*2, Vg + (size_t)rr * 3072 + cc);
            }
            CP_COMMIT();
            CP_WAIT1();
        } else {
            CP_WAIT0();
        }
        __syncthreads();
        uint32_t sK = sb + cur * FKV * 2;
        uint32_t sV = sb + (2 + cur) * FKV * 2;

        // ---- S = Q K^T ----
        float s[8][4];
        #pragma unroll
        for (int ni = 0; ni < 8; ni++)
            s[ni][0] = s[ni][1] = s[ni][2] = s[ni][3] = 0.f;
        #pragma unroll
        for (int kf = 0; kf < 4; kf++) {
            uint32_t bq[4][4];
            #pragma unroll
            for (int p = 0; p < 4; p++)
                ldsm_x4(bq[p], sK + ((16*p + brow)*FSA + 16*kf + bk)*2);
            #pragma unroll
            for (int p = 0; p < 4; p++) {
                mma_f16(s[2*p],     qa[kf], &bq[p][0]);
                mma_f16(s[2*p + 1], qa[kf], &bq[p][2]);
            }
        }

        // scale + causal mask (only last two kv tiles can violate)
        int row0 = 16*warp + g, row1 = row0 + 8;         // tile-local q rows
        bool diag = (j >= 2 * qt);
        int qg0 = 128*qt + row0, qg1 = 128*qt + row1;
        #pragma unroll
        for (int ni = 0; ni < 8; ni++) {
            int c0 = 64*j + 8*ni + 2*t4;
            s[ni][0] *= scale; s[ni][1] *= scale;
            s[ni][2] *= scale; s[ni][3] *= scale;
            if (diag) {
                if (c0     > qg0) s[ni][0] = -INFINITY;
                if (c0 + 1 > qg0) s[ni][1] = -INFINITY;
                if (c0     > qg1) s[ni][2] = -INFINITY;
                if (c0 + 1 > qg1) s[ni][3] = -INFINITY;
            }
        }

        // ---- online softmax ----
        float mt0 = -INFINITY, mt1 = -INFINITY;
        #pragma unroll
        for (int ni = 0; ni < 8; ni++) {
            mt0 = fmaxf(mt0, fmaxf(s[ni][0], s[ni][1]));
            mt1 = fmaxf(mt1, fmaxf(s[ni][2], s[ni][3]));
        }
        #pragma unroll
        for (int ofs = 1; ofs < 4; ofs <<= 1) {
            mt0 = fmaxf(mt0, __shfl_xor_sync(0xffffffffu, mt0, ofs));
            mt1 = fmaxf(mt1, __shfl_xor_sync(0xffffffffu, mt1, ofs));
        }
        float mn0 = fmaxf(m0, mt0), mn1 = fmaxf(m1, mt1);
        float al0 = __expf(m0 - mn0), al1 = __expf(m1 - mn1);
        float ps0 = 0.f, ps1 = 0.f;
        #pragma unroll
        for (int ni = 0; ni < 8; ni++) {
            s[ni][0] = __expf(s[ni][0] - mn0);
            s[ni][1] = __expf(s[ni][1] - mn0);
            s[ni][2] = __expf(s[ni][2] - mn1);
            s[ni][3] = __expf(s[ni][3] - mn1);
            ps0 += s[ni][0] + s[ni][1];
            ps1 += s[ni][2] + s[ni][3];
        }
        #pragma unroll
        for (int ofs = 1; ofs < 4; ofs <<= 1) {
            ps0 += __shfl_xor_sync(0xffffffffu, ps0, ofs);
            ps1 += __shfl_xor_sync(0xffffffffu, ps1, ofs);
        }
        m0 = mn0; m1 = mn1;
        l0 = l0 * al0 + ps0;
        l1 = l1 * al1 + ps1;
        #pragma unroll
        for (int ni = 0; ni < 8; ni++) {
            o[ni][0] *= al0; o[ni][1] *= al0;
            o[ni][2] *= al1; o[ni][3] *= al1;
        }

        // ---- P -> half smem (warp-private rows), re-fragment, O += P V ----
        #pragma unroll
        for (int ni = 0; ni < 8; ni++) {
            *(__half2*)(Ps + row0*FSA + 8*ni + 2*t4) = __floats2half2_rn(s[ni][0], s[ni][1]);
            *(__half2*)(Ps + row1*FSA + 8*ni + 2*t4) = __floats2half2_rn(s[ni][2], s[ni][3]);
        }
        __syncwarp();
        uint32_t pa[4][4];
        #pragma unroll
        for (int kf = 0; kf < 4; kf++)
            ldsm_x4(pa[kf], sP + ((16*warp + lrow)*FSA + 16*kf + lk)*2);
        #pragma unroll
        for (int kf = 0; kf < 4; kf++) {
            uint32_t vq[4][4];
            #pragma unroll
            for (int p = 0; p < 4; p++)
                ldsm_x4_t(vq[p], sV + ((16*kf + lrow)*FSA + 16*p + lk)*2);
            #pragma unroll
            for (int p = 0; p < 4; p++) {
                mma_f16(o[2*p],     pa[kf], &vq[p][0]);
                mma_f16(o[2*p + 1], pa[kf], &vq[p][2]);
            }
        }
    }

    // ---- normalize + store ----
    float inv0 = 1.f / l0, inv1 = 1.f / l1;
    int row0 = 16*warp + g;
    size_t gr0 = (size_t)(b * Nx + qt * 128 + row0) * INNERx + h * 64;
    size_t gr1 = gr0 + (size_t)8 * INNERx;
    #pragma unroll
    for (int ni = 0; ni < 8; ni++) {
        int c = 8*ni + 2*t4;
        *(__half2*)(out + gr0 + c) = __floats2half2_rn(o[ni][0]*inv0, o[ni][1]*inv0);
        *(__half2*)(out + gr1 + c) = __floats2half2_rn(o[ni][2]*inv1, o[ni][3]*inv1);
    }
}

// ---------------- halt: two-phase deterministic reduction -------------------
__global__ __launch_bounds__(256) void halt1_k(const float* __restrict__ x2,
                                               const float* __restrict__ w,
                                               double* __restrict__ hp)
{
    int blk = blockIdx.x;                       // 256 blocks
    int b = blk >> 6, sl = blk & 63;
    const int CH = Nx * Dx / 64;                // 32768
    const float* xb = x2 + (size_t)b * Nx * Dx + (size_t)sl * CH;
    double acc = 0.0;
    for (int i = threadIdx.x; i < CH; i += 256)
        acc += (double)xb[i] * (double)w[i & (Dx - 1)];
    __shared__ double sd[256];
    sd[threadIdx.x] = acc;
    __syncthreads();
    for (int s = 128; s > 0; s >>= 1) {
        if (threadIdx.x < s) sd[threadIdx.x] += sd[threadIdx.x + s];
        __syncthreads();
    }
    if (threadIdx.x == 0) hp[blk] = sd[0];
}

__global__ __launch_bounds__(32) void halt2_k(const double* __restrict__ hp,
                                              const float* __restrict__ b0,
                                              float* __restrict__ out)
{
    int t = threadIdx.x;
    if (t < 4) {
        double s = 0.0;
        for (int k = 0; k < 64; k++) s += hp[t * 64 + k];
        out[t] = (float)(s / (double)Nx) + b0[0];
    }
}

// ---------------- launch ----------------------------------------------------
extern "C" void kernel_launch(void* const* d_in, const int* in_sizes, int n_in,
                              void* d_out, int out_size)
{
    const float* x     = (const float*)d_in[0];
    const float* ln1_g = (const float*)d_in[1];
    const float* ln1_b = (const float*)d_in[2];
    const float* w_qkv = (const float*)d_in[3];
    const float* w_out = (const float*)d_in[4];
    const float* b_out = (const float*)d_in[5];
    const float* ln2_g = (const float*)d_in[6];
    const float* ln2_b = (const float*)d_in[7];
    const float* w_ff1 = (const float*)d_in[8];
    const float* b_ff1 = (const float*)d_in[9];
    const float* w_ff2 = (const float*)d_in[10];
    const float* b_ff2 = (const float*)d_in[11];
    const float* w_hlt = (const float*)d_in[12];
    const float* b_hlt = (const float*)d_in[13];

    float* out_x = (float*)d_out;
    float* out_h = out_x + (size_t)Bx * Nx * Dx;

    void *p_ln, *p_qkv, *p_att, *p_x1, *p_ff1, *p_hp;
    void *p_wqkvT, *p_woutT, *p_wff1T, *p_wff2T;
    cudaGetSymbolAddress(&p_ln, g_ln_h);
    cudaGetSymbolAddress(&p_qkv, g_qkv_h);
    cudaGetSymbolAddress(&p_att, g_att_h);
    cudaGetSymbolAddress(&p_x1, g_x1);
    cudaGetSymbolAddress(&p_ff1, g_ff1_h);
    cudaGetSymbolAddress(&p_hp, g_hp);
    cudaGetSymbolAddress(&p_wqkvT, g_wqkvT);
    cudaGetSymbolAddress(&p_woutT, g_woutT);
    cudaGetSymbolAddress(&p_wff1T, g_wff1T);
    cudaGetSymbolAddress(&p_wff2T, g_wff2T);
    __half* ln  = (__half*)p_ln;
    __half* qkv = (__half*)p_qkv;
    __half* att = (__half*)p_att;
    float*  x1  = (float*)p_x1;
    __half* ff1 = (__half*)p_ff1;

    cudaFuncSetAttribute(flashh_k, cudaFuncAttributeMaxDynamicSharedMemorySize, FLASH_SMEM);
    cudaFuncSetAttribute(hgemm<0>, cudaFuncAttributeMaxDynamicSharedMemorySize, GEMM_SMEM);
    cudaFuncSetAttribute(hgemm<1>, cudaFuncAttributeMaxDynamicSharedMemorySize, GEMM_SMEM);
    cudaFuncSetAttribute(hgemm<2>, cudaFuncAttributeMaxDynamicSharedMemorySize, GEMM_SMEM);

    // 0. weight transposes -> f16 K-major
    transpose_k<<<dim3(3*INNERx/32, Dx/32), dim3(32, 8)>>>(w_qkv, (__half*)p_wqkvT, Dx, 3*INNERx);
    transpose_k<<<dim3(Dx/32, INNERx/32),   dim3(32, 8)>>>(w_out, (__half*)p_woutT, INNERx, Dx);
    transpose_k<<<dim3(FFx/32, Dx/32),      dim3(32, 8)>>>(w_ff1, (__half*)p_wff1T, Dx, FFx);
    transpose_k<<<dim3(Dx/32, FFx/32),      dim3(32, 8)>>>(w_ff2, (__half*)p_wff2T, FFx, Dx);

    // 1. LN1 -> f16
    ln_k<<<ROWS, 256>>>(x, ln1_g, ln1_b, ln);
    // 2. QKV (f16 out)
    hgemm<0><<<dim3(3*INNERx/256, ROWS/128), 256, GEMM_SMEM>>>(
        ln, (const __half*)p_wqkvT, qkv, nullptr, nullptr, ROWS, 3*INNERx, Dx);
    // 3. causal flash attention (128-q tiles)
    flashh_k<<<dim3(Nx/128, Bx*Hx), 256, FLASH_SMEM>>>(qkv, att);
    // 4. x1 = att @ w_out + b_out + x  (f32 out)
    hgemm<1><<<dim3(Dx/256, ROWS/128), 256, GEMM_SMEM>>>(
        att, (const __half*)p_woutT, x1, b_out, x, ROWS, Dx, INNERx);
    // 5. LN2 -> f16
    ln_k<<<ROWS, 256>>>(x1, ln2_g, ln2_b, ln);
    // 6. ff1 = gelu(ln @ w_ff1 + b_ff1)  (f16 out)
    hgemm<2><<<dim3(FFx/256, ROWS/128), 256, GEMM_SMEM>>>(
        ln, (const __half*)p_wff1T, ff1, b_ff1, nullptr, ROWS, FFx, Dx);
    // 7. x2 = ff1 @ w_ff2 + b_ff2 + x1 -> d_out (f32)
    hgemm<1><<<dim3(Dx/256, ROWS/128), 256, GEMM_SMEM>>>(
        ff1, (const __half*)p_wff2T, out_x, b_ff2, x1, ROWS, Dx, FFx);
    // 8. halt (two-phase)
    halt1_k<<<256, 256>>>(out_x, w_hlt, (double*)p_hp);
    halt2_k<<<1, 32>>>((const double*)p_hp, b_hlt, out_h);
}

// round 7
// speedup vs baseline: 7.4489x; 1.0044x over previous
#include <cuda_runtime.h>
#include <cuda_fp16.h>
#include <math.h>
#include <stdint.h>

#define Bx 4
#define Nx 2048
#define Dx 1024
#define Hx 16
#define DHx 64
#define INNERx 1024
#define FFx 4096
#define ROWS (Bx*Nx)          // 8192

// ---------------- scratch ---------------------------------------------------
__device__ __half g_ln_h  [ROWS*Dx];
__device__ __half g_qkv_h [ROWS*3*INNERx];
__device__ __half g_att_h [ROWS*INNERx];
__device__ float  g_x1    [ROWS*Dx];
__device__ __half g_ff1_h [ROWS*FFx];
__device__ __half g_wqkv_h[Dx*3*INNERx];   // natural [K][N] f16
__device__ __half g_wout_h[INNERx*Dx];
__device__ __half g_wff1_h[Dx*FFx];
__device__ __half g_wff2_h[FFx*Dx];
__device__ double g_hp    [256];

// ---------------- helpers ---------------------------------------------------
__device__ __forceinline__ uint32_t u32ptr(const void* p) {
    uint32_t a;
    asm("{ .reg .u64 t; cvta.to.shared.u64 t, %1; cvt.u32.u64 %0, t; }"
        : "=r"(a) : "l"(p));
    return a;
}
__device__ __forceinline__ float gelu_exact(float v) {
    return 0.5f * v * (1.0f + erff(v * 0.70710678118654752440f));
}

#define CP_ASYNC16(dst, src) \
    asm volatile("cp.async.cg.shared.global [%0], [%1], 16;" :: "r"(dst), "l"(src))
#define CP_COMMIT() asm volatile("cp.async.commit_group;" ::: "memory")
#define CP_WAIT2()  asm volatile("cp.async.wait_group 2;" ::: "memory")
#define CP_WAIT1()  asm volatile("cp.async.wait_group 1;" ::: "memory")
#define CP_WAIT0()  asm volatile("cp.async.wait_group 0;" ::: "memory")

__device__ __forceinline__ void ldsm_x4(uint32_t* r, uint32_t addr) {
    asm volatile("ldmatrix.sync.aligned.m8n8.x4.shared.b16 {%0,%1,%2,%3}, [%4];"
        : "=r"(r[0]), "=r"(r[1]), "=r"(r[2]), "=r"(r[3]) : "r"(addr));
}
__device__ __forceinline__ void ldsm_x4_t(uint32_t* r, uint32_t addr) {
    asm volatile("ldmatrix.sync.aligned.m8n8.x4.trans.shared.b16 {%0,%1,%2,%3}, [%4];"
        : "=r"(r[0]), "=r"(r[1]), "=r"(r[2]), "=r"(r[3]) : "r"(addr));
}
__device__ __forceinline__ void mma_f16(float* d, const uint32_t* a,
                                        const uint32_t* b) {
    asm volatile(
        "mma.sync.aligned.m16n8k16.row.col.f32.f16.f16.f32 "
        "{%0,%1,%2,%3}, {%4,%5,%6,%7}, {%8,%9}, {%0,%1,%2,%3};"
        : "+f"(d[0]), "+f"(d[1]), "+f"(d[2]), "+f"(d[3])
        : "r"(a[0]), "r"(a[1]), "r"(a[2]), "r"(a[3]), "r"(b[0]), "r"(b[1]));
}

// ---------------- weight cast f32 -> f16 (natural layout) -------------------
__global__ __launch_bounds__(256) void cast_k(const float* __restrict__ W,
                                              __half* __restrict__ Wh, int n)
{
    int i = (blockIdx.x * 256 + threadIdx.x) * 4;
    if (i < n) {
        float4 v = *(const float4*)(W + i);
        __half2 h0 = __floats2half2_rn(v.x, v.y);
        __half2 h1 = __floats2half2_rn(v.z, v.w);
        *(uint2*)(Wh + i) = make_uint2(*(uint32_t*)&h0, *(uint32_t*)&h1);
    }
}

// ---------------- LayerNorm: f32 in, f16 out --------------------------------
__global__ __launch_bounds__(256) void ln_k(const float* __restrict__ x,
                                            const float* __restrict__ g,
                                            const float* __restrict__ b,
                                            __half* __restrict__ y)
{
    int row = blockIdx.x, tid = threadIdx.x;
    const float4* xr = (const float4*)(x + (size_t)row * Dx);
    float4 v = xr[tid];
    float s = v.x + v.y + v.z + v.w;
    float q = v.x*v.x + v.y*v.y + v.z*v.z + v.w*v.w;
    #pragma unroll
    for (int o = 16; o; o >>= 1) {
        s += __shfl_xor_sync(0xffffffffu, s, o);
        q += __shfl_xor_sync(0xffffffffu, q, o);
    }
    __shared__ float ss[8], qs[8];
    if ((tid & 31) == 0) { ss[tid >> 5] = s; qs[tid >> 5] = q; }
    __syncthreads();
    s = 0.f; q = 0.f;
    #pragma unroll
    for (int w = 0; w < 8; w++) { s += ss[w]; q += qs[w]; }
    float mean = s * (1.f / Dx);
    float var  = q * (1.f / Dx) - mean * mean;
    float inv  = rsqrtf(var + 1e-5f);
    float4 gv = ((const float4*)g)[tid];
    float4 bv = ((const float4*)b)[tid];
    __half2 h0 = __floats2half2_rn((v.x - mean) * inv * gv.x + bv.x,
                                   (v.y - mean) * inv * gv.y + bv.y);
    __half2 h1 = __floats2half2_rn((v.z - mean) * inv * gv.z + bv.z,
                                   (v.w - mean) * inv * gv.w + bv.w);
    uint2 pk = make_uint2(*(uint32_t*)&h0, *(uint32_t*)&h1);
    *(uint2*)(y + (size_t)row * Dx + tid * 4) = pk;
}

// ---------------- fp16 mma GEMM: 128x256 CTA, B natural [K][N], 4 stages ----
#define SA 72                                 // A row stride (halves)
#define SBn 264                               // B row stride (halves)
#define A_ST (128*SA)                         // 9216 halves
#define B_ST (64*SBn)                         // 16896 halves
#define STG  (A_ST + B_ST)                    // 26112 halves = 52224 B
#define GEMM_SMEM (4*STG*2)                   // 208896 B

template<int EPI>  // 0: half out; 1: f32 out +bias+res; 2: half out gelu(+bias)
__global__ __launch_bounds__(256) void hgemm(
    const __half* __restrict__ A, const __half* __restrict__ B,
    void* __restrict__ Cv, const float* __restrict__ bias,
    const float* __restrict__ res, int M, int N, int K)
{
    extern __shared__ __half hsm[];
    int tid = threadIdx.x, lane = tid & 31, warp = tid >> 5;
    int bm = blockIdx.y * 128, bn = blockIdx.x * 256;
    int wm = (warp >> 2) * 64, wn = (warp & 3) * 64;
    int g = lane >> 2, t4 = lane & 3;
    int lrow = lane & 15, lk = (lane >> 4) << 3;

    float acc[4][8][4];
    #pragma unroll
    for (int mi = 0; mi < 4; mi++)
        #pragma unroll
        for (int ni = 0; ni < 8; ni++)
            #pragma unroll
            for (int r = 0; r < 4; r++) acc[mi][ni][r] = 0.f;

    uint32_t sb = u32ptr(hsm);
    int arow = tid >> 3, ac8 = (tid & 7) * 8;          // A: 32 rows/iter, 64 cols
    int brow = tid >> 5, bc8 = (tid & 31) * 8;         // B: 8 rows/iter, 256 cols
    int nK = K >> 6;

    // prologue: chunks 0..2
    #pragma unroll
    for (int s = 0; s < 3; s++) {
        int kt = s * 64;
        #pragma unroll
        for (int it = 0; it < 4; it++) {
            int row = arow + it * 32;
            CP_ASYNC16(sb + (s*STG + row*SA + ac8)*2,
                       A + (size_t)(bm + row) * K + kt + ac8);
        }
        #pragma unroll
        for (int it = 0; it < 8; it++) {
            int row = brow + it * 8;
            CP_ASYNC16(sb + (s*STG + A_ST + row*SBn + bc8)*2,
                       B + (size_t)(kt + row) * N + bn + bc8);
        }
        CP_COMMIT();
    }

    for (int i = 0; i < nK; i++) {
        int rem = nK - 1 - i;
        if (rem >= 2) CP_WAIT2(); else if (rem == 1) CP_WAIT1(); else CP_WAIT0();
        __syncthreads();

        int nx = i + 3;
        if (nx < nK) {
            int ns = nx & 3, kt = nx * 64;
            #pragma unroll
            for (int it = 0; it < 4; it++) {
                int row = arow + it * 32;
                CP_ASYNC16(sb + (ns*STG + row*SA + ac8)*2,
                           A + (size_t)(bm + row) * K + kt + ac8);
            }
            #pragma unroll
            for (int it = 0; it < 8; it++) {
                int row = brow + it * 8;
                CP_ASYNC16(sb + (ns*STG + A_ST + row*SBn + bc8)*2,
                           B + (size_t)(kt + row) * N + bn + bc8);
            }
            CP_COMMIT();
        }

        uint32_t sA = sb + (i & 3) * STG * 2;
        uint32_t sB = sA + A_ST * 2;
        #pragma unroll
        for (int ks = 0; ks < 4; ks++) {
            int k = ks * 16;
            uint32_t af[4][4], bq[4][4];
            #pragma unroll
            for (int mi = 0; mi < 4; mi++)
                ldsm_x4(af[mi], sA + ((wm + 16*mi + lrow)*SA + k + lk)*2);
            #pragma unroll
            for (int p = 0; p < 4; p++)
                ldsm_x4_t(bq[p], sB + ((k + lrow)*SBn + wn + 16*p + lk)*2);
            #pragma unroll
            for (int mi = 0; mi < 4; mi++)
                #pragma unroll
                for (int p = 0; p < 4; p++) {
                    mma_f16(acc[mi][2*p],     af[mi], &bq[p][0]);
                    mma_f16(acc[mi][2*p + 1], af[mi], &bq[p][2]);
                }
        }
    }

    // epilogue
    #pragma unroll
    for (int mi = 0; mi < 4; mi++) {
        #pragma unroll
        for (int ni = 0; ni < 8; ni++) {
            int col = bn + wn + 8*ni + 2*t4;
            #pragma unroll
            for (int h = 0; h < 2; h++) {
                int row = bm + wm + 16*mi + g + 8*h;
                float v0 = acc[mi][ni][2*h + 0];
                float v1 = acc[mi][ni][2*h + 1];
                if (EPI == 0) {
                    *(__half2*)((__half*)Cv + (size_t)row * N + col) =
                        __floats2half2_rn(v0, v1);
                } else if (EPI == 1) {
                    v0 += bias[col]; v1 += bias[col + 1];
                    float2 rr = *(const float2*)(res + (size_t)row * N + col);
                    *(float2*)((float*)Cv + (size_t)row * N + col) =
                        make_float2(v0 + rr.x, v1 + rr.y);
                } else {
                    v0 = gelu_exact(v0 + bias[col]);
                    v1 = gelu_exact(v1 + bias[col + 1]);
                    *(__half2*)((__half*)Cv + (size_t)row * N + col) =
                        __floats2half2_rn(v0, v1);
                }
            }
        }
    }
}

// ---------------- fp16 flash attention: 128-q tile, 8 warps -----------------
#define FSA 72
#define FKV (64*FSA)
#define FLASH_SMEM ((4*FKV + 128*FSA)*2)     // 55296 B

__global__ __launch_bounds__(256) void flashh_k(const __half* __restrict__ qkv,
                                                __half* __restrict__ out)
{
    extern __shared__ __half fsm[];
    __half* Ps = fsm + 4 * FKV;
    uint32_t sb = u32ptr(fsm);
    uint32_t sP = sb + 4 * FKV * 2;

    int qt = blockIdx.x, bh = blockIdx.y;
    int b = bh >> 4, h = bh & 15;
    int tid = threadIdx.x, lane = tid & 31, warp = tid >> 5;
    int g = lane >> 2, t4 = lane & 3;
    int lrow = lane & 15, lk = (lane >> 4) << 3;
    int brow = (lane & 7) + ((lane & 16) >> 1);
    int bk = lane & 8;
    const float scale = 0.125f;

    size_t base = (size_t)b * Nx * 3072;
    const __half* Qg = qkv + base + (size_t)qt * 128 * 3072 + h * 64;
    int jmax = 2 * qt + 1;

    {
        #pragma unroll
        for (int it = 0; it < 4; it++) {
            int id = tid + it * 256;
            int rr = id >> 3, cc = (id & 7) * 8;
            CP_ASYNC16(sP + (rr*FSA + cc)*2, Qg + (size_t)rr * 3072 + cc);
        }
        CP_COMMIT();
        const __half* Kg = qkv + base + 1024 + h * 64;
        const __half* Vg = qkv + base + 2048 + h * 64;
        #pragma unroll
        for (int it = 0; it < 2; it++) {
            int id = tid + it * 256;
            int rr = id >> 3, cc = (id & 7) * 8;
            CP_ASYNC16(sb + (0*FKV + rr*FSA + cc)*2, Kg + (size_t)rr * 3072 + cc);
            CP_ASYNC16(sb + (2*FKV + rr*FSA + cc)*2, Vg + (size_t)rr * 3072 + cc);
        }
        CP_COMMIT();
        CP_WAIT1();
        __syncthreads();
    }

    uint32_t qa[4][4];
    #pragma unroll
    for (int kf = 0; kf < 4; kf++)
        ldsm_x4(qa[kf], sP + ((16*warp + lrow)*FSA + 16*kf + lk)*2);

    float m0 = -INFINITY, m1 = -INFINITY, l0 = 0.f, l1 = 0.f;
    float o[8][4];
    #pragma unroll
    for (int ni = 0; ni < 8; ni++)
        #pragma unroll
        for (int r = 0; r < 4; r++) o[ni][r] = 0.f;

    for (int j = 0; j <= jmax; j++) {
        __syncthreads();
        int cur = j & 1;
        if (j + 1 <= jmax) {
            int ns = (j + 1) & 1;
            const __half* Kg = qkv + base + (size_t)(j+1) * 64 * 3072 + 1024 + h * 64;
            const __half* Vg = qkv + base + (size_t)(j+1) * 64 * 3072 + 2048 + h * 64;
            #pragma unroll
            for (int it = 0; it < 2; it++) {
                int id = tid + it * 256;
                int rr = id >> 3, cc = (id & 7) * 8;
                CP_ASYNC16(sb + (ns*FKV + rr*FSA + cc)*2,     Kg + (size_t)rr * 3072 + cc);
                CP_ASYNC16(sb + ((2+ns)*FKV + rr*FSA + cc)*2, Vg + (size_t)rr * 3072 + cc);
            }
            CP_COMMIT();
            CP_WAIT1();
        } else {
            CP_WAIT0();
        }
        __syncthreads();
        uint32_t sK = sb + cur * FKV * 2;
        uint32_t sV = sb + (2 + cur) * FKV * 2;

        float s[8][4];
        #pragma unroll
        for (int ni = 0; ni < 8; ni++)
            s[ni][0] = s[ni][1] = s[ni][2] = s[ni][3] = 0.f;
        #pragma unroll
        for (int kf = 0; kf < 4; kf++) {
            uint32_t bq[4][4];
            #pragma unroll
            for (int p = 0; p < 4; p++)
                ldsm_x4(bq[p], sK + ((16*p + brow)*FSA + 16*kf + bk)*2);
            #pragma unroll
            for (int p = 0; p < 4; p++) {
                mma_f16(s[2*p],     qa[kf], &bq[p][0]);
                mma_f16(s[2*p + 1], qa[kf], &bq[p][2]);
            }
        }

        int row0 = 16*warp + g, row1 = row0 + 8;
        bool diag = (j >= 2 * qt);
        int qg0 = 128*qt + row0, qg1 = 128*qt + row1;
        #pragma unroll
        for (int ni = 0; ni < 8; ni++) {
            int c0 = 64*j + 8*ni + 2*t4;
            s[ni][0] *= scale; s[ni][1] *= scale;
            s[ni][2] *= scale; s[ni][3] *= scale;
            if (diag) {
                if (c0     > qg0) s[ni][0] = -INFINITY;
                if (c0 + 1 > qg0) s[ni][1] = -INFINITY;
                if (c0     > qg1) s[ni][2] = -INFINITY;
                if (c0 + 1 > qg1) s[ni][3] = -INFINITY;
            }
        }

        float mt0 = -INFINITY, mt1 = -INFINITY;
        #pragma unroll
        for (int ni = 0; ni < 8; ni++) {
            mt0 = fmaxf(mt0, fmaxf(s[ni][0], s[ni][1]));
            mt1 = fmaxf(mt1, fmaxf(s[ni][2], s[ni][3]));
        }
        #pragma unroll
        for (int ofs = 1; ofs < 4; ofs <<= 1) {
            mt0 = fmaxf(mt0, __shfl_xor_sync(0xffffffffu, mt0, ofs));
            mt1 = fmaxf(mt1, __shfl_xor_sync(0xffffffffu, mt1, ofs));
        }
        float mn0 = fmaxf(m0, mt0), mn1 = fmaxf(m1, mt1);
        float al0 = __expf(m0 - mn0), al1 = __expf(m1 - mn1);
        float ps0 = 0.f, ps1 = 0.f;
        #pragma unroll
        for (int ni = 0; ni < 8; ni++) {
            s[ni][0] = __expf(s[ni][0] - mn0);
            s[ni][1] = __expf(s[ni][1] - mn0);
            s[ni][2] = __expf(s[ni][2] - mn1);
            s[ni][3] = __expf(s[ni][3] - mn1);
            ps0 += s[ni][0] + s[ni][1];
            ps1 += s[ni][2] + s[ni][3];
        }
        #pragma unroll
        for (int ofs = 1; ofs < 4; ofs <<= 1) {
            ps0 += __shfl_xor_sync(0xffffffffu, ps0, ofs);
            ps1 += __shfl_xor_sync(0xffffffffu, ps1, ofs);
        }
        m0 = mn0; m1 = mn1;
        l0 = l0 * al0 + ps0;
        l1 = l1 * al1 + ps1;
        #pragma unroll
        for (int ni = 0; ni < 8; ni++) {
            o[ni][0] *= al0; o[ni][1] *= al0;
            o[ni][2] *= al1; o[ni][3] *= al1;
        }

        #pragma unroll
        for (int ni = 0; ni < 8; ni++) {
            *(__half2*)(Ps + row0*FSA + 8*ni + 2*t4) = __floats2half2_rn(s[ni][0], s[ni][1]);
            *(__half2*)(Ps + row1*FSA + 8*ni + 2*t4) = __floats2half2_rn(s[ni][2], s[ni][3]);
        }
        __syncwarp();
        uint32_t pa[4][4];
        #pragma unroll
        for (int kf = 0; kf < 4; kf++)
            ldsm_x4(pa[kf], sP + ((16*warp + lrow)*FSA + 16*kf + lk)*2);
        #pragma unroll
        for (int kf = 0; kf < 4; kf++) {
            uint32_t vq[4][4];
            #pragma unroll
            for (int p = 0; p < 4; p++)
                ldsm_x4_t(vq[p], sV + ((16*kf + lrow)*FSA + 16*p + lk)*2);
            #pragma unroll
            for (int p = 0; p < 4; p++) {
                mma_f16(o[2*p],     pa[kf], &vq[p][0]);
                mma_f16(o[2*p + 1], pa[kf], &vq[p][2]);
            }
        }
    }

    float inv0 = 1.f / l0, inv1 = 1.f / l1;
    int row0 = 16*warp + g;
    size_t gr0 = (size_t)(b * Nx + qt * 128 + row0) * INNERx + h * 64;
    size_t gr1 = gr0 + (size_t)8 * INNERx;
    #pragma unroll
    for (int ni = 0; ni < 8; ni++) {
        int c = 8*ni + 2*t4;
        *(__half2*)(out + gr0 + c) = __floats2half2_rn(o[ni][0]*inv0, o[ni][1]*inv0);
        *(__half2*)(out + gr1 + c) = __floats2half2_rn(o[ni][2]*inv1, o[ni][3]*inv1);
    }
}

// ---------------- halt: two-phase deterministic reduction -------------------
__global__ __launch_bounds__(256) void halt1_k(const float* __restrict__ x2,
                                               const float* __restrict__ w,
                                               double* __restrict__ hp)
{
    int blk = blockIdx.x;
    int b = blk >> 6, sl = blk & 63;
    const int CH = Nx * Dx / 64;
    const float* xb = x2 + (size_t)b * Nx * Dx + (size_t)sl * CH;
    double acc = 0.0;
    for (int i = threadIdx.x; i < CH; i += 256)
        acc += (double)xb[i] * (double)w[i & (Dx - 1)];
    __shared__ double sd[256];
    sd[threadIdx.x] = acc;
    __syncthreads();
    for (int s = 128; s > 0; s >>= 1) {
        if (threadIdx.x < s) sd[threadIdx.x] += sd[threadIdx.x + s];
        __syncthreads();
    }
    if (threadIdx.x == 0) hp[blk] = sd[0];
}

__global__ __launch_bounds__(32) void halt2_k(const double* __restrict__ hp,
                                              const float* __restrict__ b0,
                                              float* __restrict__ out)
{
    int t = threadIdx.x;
    if (t < 4) {
        double s = 0.0;
        for (int k = 0; k < 64; k++) s += hp[t * 64 + k];
        out[t] = (float)(s / (double)Nx) + b0[0];
    }
}

// ---------------- launch ----------------------------------------------------
extern "C" void kernel_launch(void* const* d_in, const int* in_sizes, int n_in,
                              void* d_out, int out_size)
{
    const float* x     = (const float*)d_in[0];
    const float* ln1_g = (const float*)d_in[1];
    const float* ln1_b = (const float*)d_in[2];
    const float* w_qkv = (const float*)d_in[3];
    const float* w_out = (const float*)d_in[4];
    const float* b_out = (const float*)d_in[5];
    const float* ln2_g = (const float*)d_in[6];
    const float* ln2_b = (const float*)d_in[7];
    const float* w_ff1 = (const float*)d_in[8];
    const float* b_ff1 = (const float*)d_in[9];
    const float* w_ff2 = (const float*)d_in[10];
    const float* b_ff2 = (const float*)d_in[11];
    const float* w_hlt = (const float*)d_in[12];
    const float* b_hlt = (const float*)d_in[13];

    float* out_x = (float*)d_out;
    float* out_h = out_x + (size_t)Bx * Nx * Dx;

    void *p_ln, *p_qkv, *p_att, *p_x1, *p_ff1, *p_hp;
    void *p_wqkv, *p_wout, *p_wff1, *p_wff2;
    cudaGetSymbolAddress(&p_ln, g_ln_h);
    cudaGetSymbolAddress(&p_qkv, g_qkv_h);
    cudaGetSymbolAddress(&p_att, g_att_h);
    cudaGetSymbolAddress(&p_x1, g_x1);
    cudaGetSymbolAddress(&p_ff1, g_ff1_h);
    cudaGetSymbolAddress(&p_hp, g_hp);
    cudaGetSymbolAddress(&p_wqkv, g_wqkv_h);
    cudaGetSymbolAddress(&p_wout, g_wout_h);
    cudaGetSymbolAddress(&p_wff1, g_wff1_h);
    cudaGetSymbolAddress(&p_wff2, g_wff2_h);
    __half* ln  = (__half*)p_ln;
    __half* qkv = (__half*)p_qkv;
    __half* att = (__half*)p_att;
    float*  x1  = (float*)p_x1;
    __half* ff1 = (__half*)p_ff1;

    cudaFuncSetAttribute(flashh_k, cudaFuncAttributeMaxDynamicSharedMemorySize, FLASH_SMEM);
    cudaFuncSetAttribute(hgemm<0>, cudaFuncAttributeMaxDynamicSharedMemorySize, GEMM_SMEM);
    cudaFuncSetAttribute(hgemm<1>, cudaFuncAttributeMaxDynamicSharedMemorySize, GEMM_SMEM);
    cudaFuncSetAttribute(hgemm<2>, cudaFuncAttributeMaxDynamicSharedMemorySize, GEMM_SMEM);

    // 0. weight casts -> f16 natural layout
    cast_k<<<(Dx*3*INNERx)/1024, 256>>>(w_qkv, (__half*)p_wqkv, Dx*3*INNERx);
    cast_k<<<(INNERx*Dx)/1024, 256>>>(w_out, (__half*)p_wout, INNERx*Dx);
    cast_k<<<(Dx*FFx)/1024, 256>>>(w_ff1, (__half*)p_wff1, Dx*FFx);
    cast_k<<<(FFx*Dx)/1024, 256>>>(w_ff2, (__half*)p_wff2, FFx*Dx);

    // 1. LN1 -> f16
    ln_k<<<ROWS, 256>>>(x, ln1_g, ln1_b, ln);
    // 2. QKV (f16 out)
    hgemm<0><<<dim3(3*INNERx/256, ROWS/128), 256, GEMM_SMEM>>>(
        ln, (const __half*)p_wqkv, qkv, nullptr, nullptr, ROWS, 3*INNERx, Dx);
    // 3. causal flash attention (128-q tiles)
    flashh_k<<<dim3(Nx/128, Bx*Hx), 256, FLASH_SMEM>>>(qkv, att);
    // 4. x1 = att @ w_out + b_out + x  (f32 out)
    hgemm<1><<<dim3(Dx/256, ROWS/128), 256, GEMM_SMEM>>>(
        att, (const __half*)p_wout, x1, b_out, x, ROWS, Dx, INNERx);
    // 5. LN2 -> f16
    ln_k<<<ROWS, 256>>>(x1, ln2_g, ln2_b, ln);
    // 6. ff1 = gelu(ln @ w_ff1 + b_ff1)  (f16 out)
    hgemm<2><<<dim3(FFx/256, ROWS/128), 256, GEMM_SMEM>>>(
        ln, (const __half*)p_wff1, ff1, b_ff1, nullptr, ROWS, FFx, Dx);
    // 7. x2 = ff1 @ w_ff2 + b_ff2 + x1 -> d_out (f32)
    hgemm<1><<<dim3(Dx/256, ROWS/128), 256, GEMM_SMEM>>>(
        ff1, (const __half*)p_wff2, out_x, b_ff2, x1, ROWS, Dx, FFx);
    // 8. halt
    halt1_k<<<256, 256>>>(out_x, w_hlt, (double*)p_hp);
    halt2_k<<<1, 32>>>((const double*)p_hp, b_hlt, out_h);
}